// round 1
// baseline (speedup 1.0000x reference)
#include <cuda_runtime.h>
#include <math.h>

#define Bb   2
#define LL   1024
#define DD   1024
#define HH   16
#define HDp  64
#define MM   (Bb * LL)

// Scratch (allocation-free rule: device globals)
__device__ float g_q[MM * DD];
__device__ float g_k[MM * DD];
__device__ float g_v[MM * DD];
__device__ float g_ctx[MM * DD];

// ---------------------------------------------------------------------------
// GEMM: C = A(MxK) @ W(NxK)^T + bias   (torch Linear semantics)
// 128x128 block tile, BK=16, 256 threads, 8x8 per thread (4+4 split layout).
// blockIdx.z selects among up to 3 (W, bias, C) triples (fused QKV).
// ---------------------------------------------------------------------------
__global__ __launch_bounds__(256, 2)
void gemm_nt_kernel(const float* __restrict__ A,
                    const float* __restrict__ W0, const float* __restrict__ W1,
                    const float* __restrict__ W2,
                    const float* __restrict__ b0, const float* __restrict__ b1,
                    const float* __restrict__ b2,
                    float* __restrict__ C0, float* __restrict__ C1,
                    float* __restrict__ C2,
                    int M, int N, int K)
{
    const float* W    = (blockIdx.z == 0) ? W0 : (blockIdx.z == 1 ? W1 : W2);
    const float* bias = (blockIdx.z == 0) ? b0 : (blockIdx.z == 1 ? b1 : b2);
    float*       C    = (blockIdx.z == 0) ? C0 : (blockIdx.z == 1 ? C1 : C2);

    __shared__ float As[16][132];
    __shared__ float Bs[16][132];

    const int tid = threadIdx.x;
    const int tx  = tid & 15;
    const int ty  = tid >> 4;
    const int bm  = blockIdx.y * 128;
    const int bn  = blockIdx.x * 128;

    const int lr = tid >> 2;         // 0..63
    const int lc = (tid & 3) << 2;   // 0,4,8,12

    const float* Aptr = A + (size_t)(bm + lr) * K + lc;
    const float* Wptr = W + (size_t)(bn + lr) * K + lc;

    float acc[8][8];
    #pragma unroll
    for (int i = 0; i < 8; i++)
        #pragma unroll
        for (int j = 0; j < 8; j++) acc[i][j] = 0.f;

    for (int kb = 0; kb < K; kb += 16) {
        float4 a0 = *(const float4*)(Aptr + kb);
        float4 a1 = *(const float4*)(Aptr + (size_t)64 * K + kb);
        float4 w0 = *(const float4*)(Wptr + kb);
        float4 w1 = *(const float4*)(Wptr + (size_t)64 * K + kb);
        __syncthreads();
        As[lc+0][lr]    = a0.x; As[lc+1][lr]    = a0.y; As[lc+2][lr]    = a0.z; As[lc+3][lr]    = a0.w;
        As[lc+0][lr+64] = a1.x; As[lc+1][lr+64] = a1.y; As[lc+2][lr+64] = a1.z; As[lc+3][lr+64] = a1.w;
        Bs[lc+0][lr]    = w0.x; Bs[lc+1][lr]    = w0.y; Bs[lc+2][lr]    = w0.z; Bs[lc+3][lr]    = w0.w;
        Bs[lc+0][lr+64] = w1.x; Bs[lc+1][lr+64] = w1.y; Bs[lc+2][lr+64] = w1.z; Bs[lc+3][lr+64] = w1.w;
        __syncthreads();
        #pragma unroll
        for (int k = 0; k < 16; k++) {
            float ar[8], br[8];
            #pragma unroll
            for (int i = 0; i < 4; i++) {
                ar[i]   = As[k][ty*4 + i];
                ar[4+i] = As[k][64 + ty*4 + i];
            }
            #pragma unroll
            for (int j = 0; j < 4; j++) {
                br[j]   = Bs[k][tx*4 + j];
                br[4+j] = Bs[k][64 + tx*4 + j];
            }
            #pragma unroll
            for (int i = 0; i < 8; i++)
                #pragma unroll
                for (int j = 0; j < 8; j++)
                    acc[i][j] = fmaf(ar[i], br[j], acc[i][j]);
        }
    }

    #pragma unroll
    for (int i = 0; i < 8; i++) {
        int m = bm + ((i < 4) ? (ty*4 + i) : (64 + ty*4 + (i - 4)));
        #pragma unroll
        for (int jg = 0; jg < 2; jg++) {
            int n = bn + jg*64 + tx*4;
            float4 r;
            r.x = acc[i][jg*4+0] + bias[n+0];
            r.y = acc[i][jg*4+1] + bias[n+1];
            r.z = acc[i][jg*4+2] + bias[n+2];
            r.w = acc[i][jg*4+3] + bias[n+3];
            *(float4*)(C + (size_t)m * N + n) = r;
        }
    }
}

// ---------------------------------------------------------------------------
// Flash attention with fused relative-position term.
// rel[i,j] = q_i . E[j - i + L - 2]   (zero when j - i == -(L-1))
// Block: one (b, h, 64-query tile). 256 threads as 16x16, 4x4 per thread.
// Scale (hd^-0.5 = 0.125) folded into Q at load.
// ---------------------------------------------------------------------------
#define SQS 65   // padded smem row stride (words)
#define ATT_SMEM ((4 * 64 + 127) * SQS * 4)

__global__ __launch_bounds__(256, 2)
void attn_kernel(const float* __restrict__ Q, const float* __restrict__ Kg,
                 const float* __restrict__ Vg, const float* __restrict__ E,
                 float* __restrict__ ctx)
{
    extern __shared__ float smem[];
    float* sQ = smem;                 // 64 x SQS
    float* sK = sQ + 64 * SQS;        // 64 x SQS
    float* sV = sK + 64 * SQS;        // 64 x SQS
    float* sP = sV + 64 * SQS;        // 64 x SQS
    float* sE = sP + 64 * SQS;        // 127 x SQS

    const int tid = threadIdx.x;
    const int tx  = tid & 15;
    const int ty  = tid >> 4;
    const int i0  = blockIdx.x * 64;
    const int h   = blockIdx.y;
    const int b   = blockIdx.z;

    // Load Q tile, pre-scaled
    for (int idx = tid; idx < 64 * 64; idx += 256) {
        int i = idx >> 6, d = idx & 63;
        sQ[i * SQS + d] = Q[((size_t)(b * LL + i0 + i)) * DD + h * HDp + d] * 0.125f;
    }

    float mrow[4], lrow[4], o[4][4];
    #pragma unroll
    for (int ii = 0; ii < 4; ii++) {
        mrow[ii] = -1e30f; lrow[ii] = 0.f;
        #pragma unroll
        for (int dd = 0; dd < 4; dd++) o[ii][dd] = 0.f;
    }

    for (int jt = 0; jt < LL / 64; jt++) {
        const int j0 = jt * 64;
        __syncthreads();   // previous iteration's smem reads done

        for (int idx = tid; idx < 64 * 64; idx += 256) {
            int j = idx >> 6, d = idx & 63;
            size_t g = ((size_t)(b * LL + j0 + j)) * DD + h * HDp + d;
            sK[j * SQS + d] = Kg[g];
            sV[j * SQS + d] = Vg[g];
        }
        // E band: local index li = (j - j0) - (i - i0) + 63 in [0,126]
        const int rb0 = j0 - i0 + LL - 2 - 63;
        for (int idx = tid; idx < 127 * 64; idx += 256) {
            int li = idx >> 6, d = idx & 63;
            int r = rb0 + li;
            sE[li * SQS + d] = (r >= 0) ? E[(size_t)r * HDp + d] : 0.f;
        }
        __syncthreads();

        // S = Q (K + E_band)^T   -- 4x4 accum per thread
        float acc[4][4];
        #pragma unroll
        for (int ii = 0; ii < 4; ii++)
            #pragma unroll
            for (int jj = 0; jj < 4; jj++) acc[ii][jj] = 0.f;

        const int lbase = 4 * (tx - ty) + 60;  // row for delta = -3
        #pragma unroll 4
        for (int d = 0; d < 64; d++) {
            float qf[4], kf[4], ef[7];
            #pragma unroll
            for (int ii = 0; ii < 4; ii++) qf[ii] = sQ[(ty*4 + ii) * SQS + d];
            #pragma unroll
            for (int jj = 0; jj < 4; jj++) kf[jj] = sK[(tx*4 + jj) * SQS + d];
            #pragma unroll
            for (int t = 0; t < 7; t++)   ef[t]  = sE[(lbase + t) * SQS + d];
            #pragma unroll
            for (int ii = 0; ii < 4; ii++)
                #pragma unroll
                for (int jj = 0; jj < 4; jj++)
                    acc[ii][jj] = fmaf(qf[ii], kf[jj] + ef[jj - ii + 3], acc[ii][jj]);
        }

        // Online softmax (row groups = 16 lanes sharing ty; shfl within half-warp)
        #pragma unroll
        for (int ii = 0; ii < 4; ii++) {
            float rmax = fmaxf(fmaxf(acc[ii][0], acc[ii][1]),
                               fmaxf(acc[ii][2], acc[ii][3]));
            #pragma unroll
            for (int off = 8; off >= 1; off >>= 1)
                rmax = fmaxf(rmax, __shfl_xor_sync(0xffffffffu, rmax, off));
            float mnew = fmaxf(mrow[ii], rmax);
            float corr = __expf(mrow[ii] - mnew);
            float p[4];
            float rs = 0.f;
            #pragma unroll
            for (int jj = 0; jj < 4; jj++) {
                p[jj] = __expf(acc[ii][jj] - mnew);
                rs += p[jj];
            }
            #pragma unroll
            for (int off = 8; off >= 1; off >>= 1)
                rs += __shfl_xor_sync(0xffffffffu, rs, off);
            lrow[ii] = lrow[ii] * corr + rs;
            mrow[ii] = mnew;
            #pragma unroll
            for (int dd = 0; dd < 4; dd++) o[ii][dd] *= corr;
            #pragma unroll
            for (int jj = 0; jj < 4; jj++)
                sP[(ty*4 + ii) * SQS + tx*4 + jj] = p[jj];
        }
        __syncthreads();

        // O += P @ V
        #pragma unroll 8
        for (int j = 0; j < 64; j++) {
            float pf[4], vf[4];
            #pragma unroll
            for (int ii = 0; ii < 4; ii++) pf[ii] = sP[(ty*4 + ii) * SQS + j];
            #pragma unroll
            for (int dd = 0; dd < 4; dd++) vf[dd] = sV[j * SQS + tx*4 + dd];
            #pragma unroll
            for (int ii = 0; ii < 4; ii++)
                #pragma unroll
                for (int dd = 0; dd < 4; dd++)
                    o[ii][dd] = fmaf(pf[ii], vf[dd], o[ii][dd]);
        }
    }

    // Epilogue: normalize, write ctx in (B, L, D) layout for the output GEMM
    #pragma unroll
    for (int ii = 0; ii < 4; ii++) {
        float inv = 1.f / lrow[ii];
        size_t base = ((size_t)(b * LL + i0 + ty*4 + ii)) * DD + h * HDp + tx*4;
        float4 r;
        r.x = o[ii][0] * inv; r.y = o[ii][1] * inv;
        r.z = o[ii][2] * inv; r.w = o[ii][3] * inv;
        *(float4*)(ctx + base) = r;
    }
}

// ---------------------------------------------------------------------------
extern "C" void kernel_launch(void* const* d_in, const int* in_sizes, int n_in,
                              void* d_out, int out_size)
{
    const float* x  = (const float*)d_in[0];
    const float* Wq = (const float*)d_in[1];
    const float* bq = (const float*)d_in[2];
    const float* Wk = (const float*)d_in[3];
    const float* bk = (const float*)d_in[4];
    const float* Wv = (const float*)d_in[5];
    const float* bv = (const float*)d_in[6];
    const float* Wo = (const float*)d_in[7];
    const float* bo = (const float*)d_in[8];
    const float* E  = (const float*)d_in[9];
    float* out = (float*)d_out;

    float *q, *k, *v, *ctx;
    cudaGetSymbolAddress((void**)&q,   g_q);
    cudaGetSymbolAddress((void**)&k,   g_k);
    cudaGetSymbolAddress((void**)&v,   g_v);
    cudaGetSymbolAddress((void**)&ctx, g_ctx);

    cudaFuncSetAttribute(attn_kernel,
                         cudaFuncAttributeMaxDynamicSharedMemorySize, ATT_SMEM);

    // 1) Fused QKV projections
    gemm_nt_kernel<<<dim3(DD/128, MM/128, 3), 256>>>(
        x, Wq, Wk, Wv, bq, bk, bv, q, k, v, MM, DD, DD);

    // 2) Fused rel-pos flash attention
    attn_kernel<<<dim3(LL/64, HH, Bb), 256, ATT_SMEM>>>(q, k, v, E, ctx);

    // 3) Output projection
    gemm_nt_kernel<<<dim3(DD/128, MM/128, 1), 256>>>(
        ctx, Wo, Wo, Wo, bo, bo, bo, out, out, out, MM, DD, DD);
}

// round 2
// speedup vs baseline: 1.2241x; 1.2241x over previous
#include <cuda_runtime.h>
#include <math.h>

#define Bb   2
#define LL   1024
#define DD   1024
#define HH   16
#define HDp  64
#define MM   (Bb * LL)

// Scratch (allocation-free rule: device globals)
__device__ float g_q[MM * DD];
__device__ float g_k[MM * DD];
__device__ float g_v[MM * DD];
__device__ float g_ctx[MM * DD];

// ---------------------------------------------------------------------------
// GEMM: C = A(MxK) @ W(NxK)^T + bias, 128x128 tile, BK=16, 256 thr, 8x8/thr.
// Double-buffered smem: one barrier per k-iter.
// ---------------------------------------------------------------------------
__global__ __launch_bounds__(256, 2)
void gemm_nt_kernel(const float* __restrict__ A,
                    const float* __restrict__ W0, const float* __restrict__ W1,
                    const float* __restrict__ W2,
                    const float* __restrict__ b0, const float* __restrict__ b1,
                    const float* __restrict__ b2,
                    float* __restrict__ C0, float* __restrict__ C1,
                    float* __restrict__ C2,
                    int M, int N, int K)
{
    const float* W    = (blockIdx.z == 0) ? W0 : (blockIdx.z == 1 ? W1 : W2);
    const float* bias = (blockIdx.z == 0) ? b0 : (blockIdx.z == 1 ? b1 : b2);
    float*       C    = (blockIdx.z == 0) ? C0 : (blockIdx.z == 1 ? C1 : C2);

    __shared__ float As[2][16][132];
    __shared__ float Bs[2][16][132];

    const int tid = threadIdx.x;
    const int tx  = tid & 15;
    const int ty  = tid >> 4;
    const int bm  = blockIdx.y * 128;
    const int bn  = blockIdx.x * 128;

    const int lr = tid >> 2;         // 0..63
    const int lc = (tid & 3) << 2;   // 0,4,8,12

    const float* Aptr = A + (size_t)(bm + lr) * K + lc;
    const float* Wptr = W + (size_t)(bn + lr) * K + lc;

    float acc[8][8];
    #pragma unroll
    for (int i = 0; i < 8; i++)
        #pragma unroll
        for (int j = 0; j < 8; j++) acc[i][j] = 0.f;

    // prologue: stage 0
    {
        float4 a0 = *(const float4*)(Aptr);
        float4 a1 = *(const float4*)(Aptr + (size_t)64 * K);
        float4 w0 = *(const float4*)(Wptr);
        float4 w1 = *(const float4*)(Wptr + (size_t)64 * K);
        As[0][lc+0][lr]    = a0.x; As[0][lc+1][lr]    = a0.y; As[0][lc+2][lr]    = a0.z; As[0][lc+3][lr]    = a0.w;
        As[0][lc+0][lr+64] = a1.x; As[0][lc+1][lr+64] = a1.y; As[0][lc+2][lr+64] = a1.z; As[0][lc+3][lr+64] = a1.w;
        Bs[0][lc+0][lr]    = w0.x; Bs[0][lc+1][lr]    = w0.y; Bs[0][lc+2][lr]    = w0.z; Bs[0][lc+3][lr]    = w0.w;
        Bs[0][lc+0][lr+64] = w1.x; Bs[0][lc+1][lr+64] = w1.y; Bs[0][lc+2][lr+64] = w1.z; Bs[0][lc+3][lr+64] = w1.w;
    }
    __syncthreads();

    int cur = 0;
    for (int kb = 0; kb < K; kb += 16) {
        const int nxt = kb + 16;
        float4 na0, na1, nw0, nw1;
        const bool has = (nxt < K);
        if (has) {
            na0 = *(const float4*)(Aptr + nxt);
            na1 = *(const float4*)(Aptr + (size_t)64 * K + nxt);
            nw0 = *(const float4*)(Wptr + nxt);
            nw1 = *(const float4*)(Wptr + (size_t)64 * K + nxt);
        }
        #pragma unroll
        for (int k = 0; k < 16; k++) {
            float ar[8], br[8];
            #pragma unroll
            for (int i = 0; i < 4; i++) {
                ar[i]   = As[cur][k][ty*4 + i];
                ar[4+i] = As[cur][k][64 + ty*4 + i];
            }
            #pragma unroll
            for (int j = 0; j < 4; j++) {
                br[j]   = Bs[cur][k][tx*4 + j];
                br[4+j] = Bs[cur][k][64 + tx*4 + j];
            }
            #pragma unroll
            for (int i = 0; i < 8; i++)
                #pragma unroll
                for (int j = 0; j < 8; j++)
                    acc[i][j] = fmaf(ar[i], br[j], acc[i][j]);
        }
        if (has) {
            const int nb = cur ^ 1;
            As[nb][lc+0][lr]    = na0.x; As[nb][lc+1][lr]    = na0.y; As[nb][lc+2][lr]    = na0.z; As[nb][lc+3][lr]    = na0.w;
            As[nb][lc+0][lr+64] = na1.x; As[nb][lc+1][lr+64] = na1.y; As[nb][lc+2][lr+64] = na1.z; As[nb][lc+3][lr+64] = na1.w;
            Bs[nb][lc+0][lr]    = nw0.x; Bs[nb][lc+1][lr]    = nw0.y; Bs[nb][lc+2][lr]    = nw0.z; Bs[nb][lc+3][lr]    = nw0.w;
            Bs[nb][lc+0][lr+64] = nw1.x; Bs[nb][lc+1][lr+64] = nw1.y; Bs[nb][lc+2][lr+64] = nw1.z; Bs[nb][lc+3][lr+64] = nw1.w;
            __syncthreads();
            cur = nb;
        }
    }

    #pragma unroll
    for (int i = 0; i < 8; i++) {
        int m = bm + ((i < 4) ? (ty*4 + i) : (64 + ty*4 + (i - 4)));
        #pragma unroll
        for (int jg = 0; jg < 2; jg++) {
            int n = bn + jg*64 + tx*4;
            float4 r;
            r.x = acc[i][jg*4+0] + bias[n+0];
            r.y = acc[i][jg*4+1] + bias[n+1];
            r.z = acc[i][jg*4+2] + bias[n+2];
            r.w = acc[i][jg*4+3] + bias[n+3];
            *(float4*)(C + (size_t)m * N + n) = r;
        }
    }
}

// ---------------------------------------------------------------------------
// Flash attention with fused relative-position term.
// rel[i,j] = q_i . E[j - i + L - 2]   (zero when j - i == -(L-1))
// 128-query x 128-key tiles, 256 threads, 8x8 per thread with STRIDED lane
// mapping (rows i = ty + 16*ii, cols j = tx + 16*jj) so strided smem reads
// hit distinct banks. Head dim split d = tx*4 + dd for the PV/output phase.
// P is staged in registers (reusing acc) and aliased onto the E smem region.
// ---------------------------------------------------------------------------
#define SQl 64
#define SKl 65
#define SVl 64
#define SEl 65
#define SPl 128
#define K_OFF  (128 * SQl)              // 8192
#define V_OFF  (K_OFF + 128 * SKl)      // 16512
#define EP_OFF (V_OFF + 128 * SVl)      // 24704
#define EP_SZ  16575                    // max(255*65, 128*128)
#define ATT_SMEM ((EP_OFF + EP_SZ) * 4) // 165116 B

__global__ __launch_bounds__(256, 1)
void attn_kernel(const float* __restrict__ Q, const float* __restrict__ Kg,
                 const float* __restrict__ Vg, const float* __restrict__ E,
                 float* __restrict__ ctx)
{
    extern __shared__ float sm[];
    float* sQ  = sm;
    float* sK  = sm + K_OFF;
    float* sV  = sm + V_OFF;
    float* sEP = sm + EP_OFF;   // E band during score; P during PV

    const int tid = threadIdx.x;
    const int tx  = tid & 15;
    const int ty  = tid >> 4;
    const int i0  = blockIdx.x * 128;
    const int h   = blockIdx.y;
    const int b   = blockIdx.z;

    // Load Q tile (pre-scaled by hd^-0.5 = 0.125)
    const float* gq = Q + ((size_t)(b * LL + i0)) * DD + h * HDp;
    for (int idx = tid; idx < 2048; idx += 256) {
        int r = idx >> 4, c4 = (idx & 15) << 2;
        float4 v = *(const float4*)(gq + (size_t)r * DD + c4);
        v.x *= 0.125f; v.y *= 0.125f; v.z *= 0.125f; v.w *= 0.125f;
        *(float4*)(sQ + r * SQl + c4) = v;
    }

    float mrow[8], lrow[8], o[8][4];
    #pragma unroll
    for (int ii = 0; ii < 8; ii++) {
        mrow[ii] = -1e30f; lrow[ii] = 0.f;
        #pragma unroll
        for (int dd = 0; dd < 4; dd++) o[ii][dd] = 0.f;
    }

    const float* bq  = sQ + ty * SQl;              // qf[ii] = bq[ii*16*SQl + d]
    const float* bk  = sK + tx * SKl;              // kf[jj] = bk[jj*16*SKl + d]
    const float* be  = sEP + (tx - ty + 15) * SEl; // ef[t]  = be[t*16*SEl + d]
    float*       bpw = sEP + ty * SPl + tx;        // P write
    const float* bpr = sEP + ty * SPl;             // P read
    const float* bv  = sV + tx * 4;                // vf float4 at bv[j*SVl]

    for (int jt = 0; jt < LL / 128; jt++) {
        const int j0 = jt * 128;
        __syncthreads();   // previous iteration's smem reads done

        // Load K, V tiles
        const float* gk = Kg + ((size_t)(b * LL + j0)) * DD + h * HDp;
        const float* gv = Vg + ((size_t)(b * LL + j0)) * DD + h * HDp;
        for (int idx = tid; idx < 2048; idx += 256) {
            int r = idx >> 4, c4 = (idx & 15) << 2;
            float4 kv = *(const float4*)(gk + (size_t)r * DD + c4);
            float* dk = sK + r * SKl + c4;
            dk[0] = kv.x; dk[1] = kv.y; dk[2] = kv.z; dk[3] = kv.w;
            float4 vv = *(const float4*)(gv + (size_t)r * DD + c4);
            *(float4*)(sV + r * SVl + c4) = vv;
        }
        // E band: li in [0,254], global row r = rb0 + li, zero when r < 0
        const int rb0 = 895 + j0 - i0;
        for (int idx = tid; idx < 255 * 16; idx += 256) {
            int li = idx >> 4, c4 = (idx & 15) << 2;
            int r = rb0 + li;
            float4 ev = make_float4(0.f, 0.f, 0.f, 0.f);
            if (r >= 0) ev = *(const float4*)(E + (size_t)r * HDp + c4);
            float* de = sEP + li * SEl + c4;
            de[0] = ev.x; de[1] = ev.y; de[2] = ev.z; de[3] = ev.w;
        }
        __syncthreads();

        // S = Q (K + E_band)^T, 8x8 per thread
        float acc[8][8];
        #pragma unroll
        for (int ii = 0; ii < 8; ii++)
            #pragma unroll
            for (int jj = 0; jj < 8; jj++) acc[ii][jj] = 0.f;

        #pragma unroll 2
        for (int d = 0; d < 64; d++) {
            float qf[8], kf[8], ef[15];
            #pragma unroll
            for (int ii = 0; ii < 8; ii++) qf[ii] = bq[ii * (16 * SQl) + d];
            #pragma unroll
            for (int jj = 0; jj < 8; jj++) kf[jj] = bk[jj * (16 * SKl) + d];
            #pragma unroll
            for (int t = 0; t < 15; t++)  ef[t]  = be[t * (16 * SEl) + d];
            #pragma unroll
            for (int ii = 0; ii < 8; ii++)
                #pragma unroll
                for (int jj = 0; jj < 8; jj++)
                    acc[ii][jj] = fmaf(qf[ii], kf[jj] + ef[jj - ii + 7], acc[ii][jj]);
        }

        // Online softmax; rows live in 16-lane half-warp groups
        #pragma unroll
        for (int ii = 0; ii < 8; ii++) {
            float rmax = acc[ii][0];
            #pragma unroll
            for (int jj = 1; jj < 8; jj++) rmax = fmaxf(rmax, acc[ii][jj]);
            #pragma unroll
            for (int off = 8; off >= 1; off >>= 1)
                rmax = fmaxf(rmax, __shfl_xor_sync(0xffffffffu, rmax, off));
            float mnew = fmaxf(mrow[ii], rmax);
            float corr = __expf(mrow[ii] - mnew);
            float rs = 0.f;
            #pragma unroll
            for (int jj = 0; jj < 8; jj++) {
                float p = __expf(acc[ii][jj] - mnew);
                acc[ii][jj] = p;
                rs += p;
            }
            #pragma unroll
            for (int off = 8; off >= 1; off >>= 1)
                rs += __shfl_xor_sync(0xffffffffu, rs, off);
            lrow[ii] = lrow[ii] * corr + rs;
            mrow[ii] = mnew;
            #pragma unroll
            for (int dd = 0; dd < 4; dd++) o[ii][dd] *= corr;
        }
        __syncthreads();   // all E reads done before P overwrites the region

        #pragma unroll
        for (int ii = 0; ii < 8; ii++)
            #pragma unroll
            for (int jj = 0; jj < 8; jj++)
                bpw[ii * (16 * SPl) + jj * 16] = acc[ii][jj];
        __syncthreads();

        // O += P @ V
        #pragma unroll 2
        for (int j = 0; j < 128; j++) {
            float pf[8];
            #pragma unroll
            for (int ii = 0; ii < 8; ii++) pf[ii] = bpr[ii * (16 * SPl) + j];
            float4 vv = *(const float4*)(bv + j * SVl);
            #pragma unroll
            for (int ii = 0; ii < 8; ii++) {
                o[ii][0] = fmaf(pf[ii], vv.x, o[ii][0]);
                o[ii][1] = fmaf(pf[ii], vv.y, o[ii][1]);
                o[ii][2] = fmaf(pf[ii], vv.z, o[ii][2]);
                o[ii][3] = fmaf(pf[ii], vv.w, o[ii][3]);
            }
        }
    }

    // Epilogue: normalize and store ctx in (B, L, D) layout
    float* gc = ctx + ((size_t)(b * LL + i0)) * DD + h * HDp + tx * 4;
    #pragma unroll
    for (int ii = 0; ii < 8; ii++) {
        float inv = 1.f / lrow[ii];
        float4 r;
        r.x = o[ii][0] * inv; r.y = o[ii][1] * inv;
        r.z = o[ii][2] * inv; r.w = o[ii][3] * inv;
        *(float4*)(gc + (size_t)(ty + 16 * ii) * DD) = r;
    }
}

// ---------------------------------------------------------------------------
extern "C" void kernel_launch(void* const* d_in, const int* in_sizes, int n_in,
                              void* d_out, int out_size)
{
    const float* x  = (const float*)d_in[0];
    const float* Wq = (const float*)d_in[1];
    const float* bq = (const float*)d_in[2];
    const float* Wk = (const float*)d_in[3];
    const float* bk = (const float*)d_in[4];
    const float* Wv = (const float*)d_in[5];
    const float* bv = (const float*)d_in[6];
    const float* Wo = (const float*)d_in[7];
    const float* bo = (const float*)d_in[8];
    const float* E  = (const float*)d_in[9];
    float* out = (float*)d_out;

    float *q, *k, *v, *ctx;
    cudaGetSymbolAddress((void**)&q,   g_q);
    cudaGetSymbolAddress((void**)&k,   g_k);
    cudaGetSymbolAddress((void**)&v,   g_v);
    cudaGetSymbolAddress((void**)&ctx, g_ctx);

    cudaFuncSetAttribute(attn_kernel,
                         cudaFuncAttributeMaxDynamicSharedMemorySize, ATT_SMEM);

    // 1) Fused QKV projections
    gemm_nt_kernel<<<dim3(DD/128, MM/128, 3), 256>>>(
        x, Wq, Wk, Wv, bq, bk, bv, q, k, v, MM, DD, DD);

    // 2) Fused rel-pos flash attention
    attn_kernel<<<dim3(LL/128, HH, Bb), 256, ATT_SMEM>>>(q, k, v, E, ctx);

    // 3) Output projection
    gemm_nt_kernel<<<dim3(DD/128, MM/128, 1), 256>>>(
        ctx, Wo, Wo, Wo, bo, bo, bo, out, out, out, MM, DD, DD);
}

// round 4
// speedup vs baseline: 1.5071x; 1.2312x over previous
#include <cuda_runtime.h>
#include <cuda_bf16.h>
#include <math.h>
#include <cstdint>

#define Bb   2
#define LL   1024
#define DD   1024
#define HH   16
#define HDp  64
#define MM   (Bb * LL)

// Scratch (allocation-free rule: device globals)
__device__ float g_q[MM * DD];
__device__ float g_k[MM * DD];
__device__ float g_v[MM * DD];
__device__ float g_ctx[MM * DD];

// ===========================================================================
// Warp-MMA helpers (sm_80+ ISA; works on plain sm_103 target)
// ===========================================================================
__device__ __forceinline__ uint32_t smem_u32(const void* p) {
    uint32_t a;
    asm("{ .reg .u64 t; cvta.to.shared.u64 t, %1; cvt.u32.u64 %0, t; }"
        : "=r"(a) : "l"(p));
    return a;
}
__device__ __forceinline__ void ldsm_x4(uint32_t addr, uint32_t r[4]) {
    asm volatile("ldmatrix.sync.aligned.m8n8.x4.shared.b16 {%0,%1,%2,%3}, [%4];"
                 : "=r"(r[0]), "=r"(r[1]), "=r"(r[2]), "=r"(r[3]) : "r"(addr));
}
__device__ __forceinline__ void mma_bf16(float c[4], const uint32_t a[4],
                                         uint32_t b0, uint32_t b1) {
    asm volatile(
        "mma.sync.aligned.m16n8k16.row.col.f32.bf16.bf16.f32 "
        "{%0,%1,%2,%3}, {%4,%5,%6,%7}, {%8,%9}, {%0,%1,%2,%3};"
        : "+f"(c[0]), "+f"(c[1]), "+f"(c[2]), "+f"(c[3])
        : "r"(a[0]), "r"(a[1]), "r"(a[2]), "r"(a[3]), "r"(b0), "r"(b1));
}
__device__ __forceinline__ uint32_t pack2(__nv_bfloat16 a, __nv_bfloat16 b) {
    return (uint32_t)__bfloat16_as_ushort(a) | ((uint32_t)__bfloat16_as_ushort(b) << 16);
}
// Convert 8 consecutive fp32 -> 8 bf16 hi + 8 bf16 lo (residual)
__device__ __forceinline__ void cvt8(const float* p, uint4& hi, uint4& lo) {
    float4 f0 = *(const float4*)p;
    float4 f1 = *(const float4*)(p + 4);
    float vv[8] = {f0.x, f0.y, f0.z, f0.w, f1.x, f1.y, f1.z, f1.w};
    __nv_bfloat16 hb[8], lb[8];
    #pragma unroll
    for (int e = 0; e < 8; e++) {
        hb[e] = __float2bfloat16(vv[e]);
        lb[e] = __float2bfloat16(vv[e] - __bfloat162float(hb[e]));
    }
    hi.x = pack2(hb[0], hb[1]); hi.y = pack2(hb[2], hb[3]);
    hi.z = pack2(hb[4], hb[5]); hi.w = pack2(hb[6], hb[7]);
    lo.x = pack2(lb[0], lb[1]); lo.y = pack2(lb[2], lb[3]);
    lo.z = pack2(lb[4], lb[5]); lo.w = pack2(lb[6], lb[7]);
}

// ===========================================================================
// Tensor-core GEMM: C = A(MxK) @ W(NxK)^T + bias, bf16 hi/lo split (3 MMAs).
// 128x128 CTA tile, 8 warps (2m x 4n), warp tile 64x32. K chunks of 64.
// smem: 4 tiles (Ahi, Alo, Bhi, Blo), 128 rows x 72 bf16 (144B stride).
// ===========================================================================
#define GSA     144                      // smem row stride, bytes
#define GTILE_B (128 * GSA)              // 18432 B per split-matrix
#define OFF_AHI 0
#define OFF_ALO GTILE_B
#define OFF_BHI (2 * GTILE_B)
#define OFF_BLO (3 * GTILE_B)
#define GEMM_SMEM (4 * GTILE_B)          // 73728 B

__global__ __launch_bounds__(256, 2)
void gemm_tc_kernel(const float* __restrict__ A,
                    const float* __restrict__ W0, const float* __restrict__ W1,
                    const float* __restrict__ W2,
                    const float* __restrict__ b0, const float* __restrict__ b1,
                    const float* __restrict__ b2,
                    float* __restrict__ C0, float* __restrict__ C1,
                    float* __restrict__ C2,
                    int M, int N, int K)
{
    const float* W    = (blockIdx.z == 0) ? W0 : (blockIdx.z == 1 ? W1 : W2);
    const float* bias = (blockIdx.z == 0) ? b0 : (blockIdx.z == 1 ? b1 : b2);
    float*       C    = (blockIdx.z == 0) ? C0 : (blockIdx.z == 1 ? C1 : C2);

    extern __shared__ char sm[];
    const uint32_t sbase = smem_u32(sm);

    const int tid  = threadIdx.x;
    const int lane = tid & 31;
    const int wid  = tid >> 5;
    const int wm   = wid & 1;            // 0..1  (64 rows each)
    const int wn   = wid >> 1;           // 0..3  (32 cols each)
    const int bm   = blockIdx.y * 128;
    const int bn   = blockIdx.x * 128;

    float acc[4][4][4];                  // [mi][nj][reg], m16n8 tiles
    #pragma unroll
    for (int i = 0; i < 4; i++)
        #pragma unroll
        for (int j = 0; j < 4; j++)
            #pragma unroll
            for (int r = 0; r < 4; r++) acc[i][j][r] = 0.f;

    // fill mapping: row = tid>>1 (128 rows), col half = (tid&1)*32
    const int frow = tid >> 1;
    const int fcol = (tid & 1) * 32;
    const float* pa = A + (size_t)(bm + frow) * K + fcol;
    const float* pw = W + (size_t)(bn + frow) * K + fcol;
    char* frowp = sm + frow * GSA + fcol * 2;

    // ldmatrix lane addressing: row offset (lane&15), col byte (lane>>4)*16
    const int lr   = lane & 15;
    const int lc16 = (lane >> 4) * 16;
    const uint32_t a_lane = sbase + (uint32_t)((wm * 64 + lr) * GSA + lc16);
    const uint32_t b_lane = sbase + (uint32_t)((wn * 32 + lr) * GSA + lc16);

    for (int c = 0; c < K / 64; c++) {
        const int kb = c * 64;
        __syncthreads();
        #pragma unroll
        for (int g = 0; g < 4; g++) {
            uint4 hi, lo;
            cvt8(pa + kb + g * 8, hi, lo);
            *(uint4*)(frowp + OFF_AHI + g * 16) = hi;
            *(uint4*)(frowp + OFF_ALO + g * 16) = lo;
            cvt8(pw + kb + g * 8, hi, lo);
            *(uint4*)(frowp + OFF_BHI + g * 16) = hi;
            *(uint4*)(frowp + OFF_BLO + g * 16) = lo;
        }
        __syncthreads();

        #pragma unroll
        for (int ks = 0; ks < 4; ks++) {
            const uint32_t cb = (uint32_t)(ks * 32);
            uint32_t ah[4][4], al[4][4];
            #pragma unroll
            for (int mi = 0; mi < 4; mi++) {
                ldsm_x4(a_lane + OFF_AHI + mi * (16 * GSA) + cb, ah[mi]);
                ldsm_x4(a_lane + OFF_ALO + mi * (16 * GSA) + cb, al[mi]);
            }
            #pragma unroll
            for (int nb = 0; nb < 2; nb++) {
                uint32_t bh[4], bl[4];
                ldsm_x4(b_lane + OFF_BHI + nb * (16 * GSA) + cb, bh);
                ldsm_x4(b_lane + OFF_BLO + nb * (16 * GSA) + cb, bl);
                #pragma unroll
                for (int mi = 0; mi < 4; mi++) {
                    // n8 block 0 of this n16: frag {bh[0], bh[2]}
                    mma_bf16(acc[mi][2*nb],   ah[mi], bh[0], bh[2]);
                    mma_bf16(acc[mi][2*nb],   ah[mi], bl[0], bl[2]);
                    mma_bf16(acc[mi][2*nb],   al[mi], bh[0], bh[2]);
                    // n8 block 1: frag {bh[1], bh[3]}
                    mma_bf16(acc[mi][2*nb+1], ah[mi], bh[1], bh[3]);
                    mma_bf16(acc[mi][2*nb+1], ah[mi], bl[1], bl[3]);
                    mma_bf16(acc[mi][2*nb+1], al[mi], bh[1], bh[3]);
                }
            }
        }
    }

    // Epilogue
    const int ql = lane >> 2;            // 0..7  (m within frag)
    const int rl = (lane & 3) * 2;       // n pair within n8
    #pragma unroll
    for (int mi = 0; mi < 4; mi++) {
        const int m = bm + wm * 64 + mi * 16 + ql;
        #pragma unroll
        for (int nj = 0; nj < 4; nj++) {
            const int n = bn + wn * 32 + nj * 8 + rl;
            const float bz0 = bias[n], bz1 = bias[n + 1];
            float2 v;
            v.x = acc[mi][nj][0] + bz0; v.y = acc[mi][nj][1] + bz1;
            *(float2*)(C + (size_t)m * N + n) = v;
            v.x = acc[mi][nj][2] + bz0; v.y = acc[mi][nj][3] + bz1;
            *(float2*)(C + (size_t)(m + 8) * N + n) = v;
        }
    }
}

// ---------------------------------------------------------------------------
// Flash attention with fused relative-position term (unchanged from R2).
// rel[i,j] = q_i . E[j - i + L - 2]   (zero when j - i == -(L-1))
// ---------------------------------------------------------------------------
#define SQl 64
#define SKl 65
#define SVl 64
#define SEl 65
#define SPl 128
#define K_OFF  (128 * SQl)
#define V_OFF  (K_OFF + 128 * SKl)
#define EP_OFF (V_OFF + 128 * SVl)
#define EP_SZ  16575
#define ATT_SMEM ((EP_OFF + EP_SZ) * 4)

__global__ __launch_bounds__(256, 1)
void attn_kernel(const float* __restrict__ Q, const float* __restrict__ Kg,
                 const float* __restrict__ Vg, const float* __restrict__ E,
                 float* __restrict__ ctx)
{
    extern __shared__ float smf[];
    float* sQ  = smf;
    float* sK  = smf + K_OFF;
    float* sV  = smf + V_OFF;
    float* sEP = smf + EP_OFF;

    const int tid = threadIdx.x;
    const int tx  = tid & 15;
    const int ty  = tid >> 4;
    const int i0  = blockIdx.x * 128;
    const int h   = blockIdx.y;
    const int b   = blockIdx.z;

    const float* gq = Q + ((size_t)(b * LL + i0)) * DD + h * HDp;
    for (int idx = tid; idx < 2048; idx += 256) {
        int r = idx >> 4, c4 = (idx & 15) << 2;
        float4 v = *(const float4*)(gq + (size_t)r * DD + c4);
        v.x *= 0.125f; v.y *= 0.125f; v.z *= 0.125f; v.w *= 0.125f;
        *(float4*)(sQ + r * SQl + c4) = v;
    }

    float mrow[8], lrow[8], o[8][4];
    #pragma unroll
    for (int ii = 0; ii < 8; ii++) {
        mrow[ii] = -1e30f; lrow[ii] = 0.f;
        #pragma unroll
        for (int dd = 0; dd < 4; dd++) o[ii][dd] = 0.f;
    }

    const float* bq  = sQ + ty * SQl;
    const float* bk  = sK + tx * SKl;
    const float* be  = sEP + (tx - ty + 15) * SEl;
    float*       bpw = sEP + ty * SPl + tx;
    const float* bpr = sEP + ty * SPl;
    const float* bv  = sV + tx * 4;

    for (int jt = 0; jt < LL / 128; jt++) {
        const int j0 = jt * 128;
        __syncthreads();

        const float* gk = Kg + ((size_t)(b * LL + j0)) * DD + h * HDp;
        const float* gv = Vg + ((size_t)(b * LL + j0)) * DD + h * HDp;
        for (int idx = tid; idx < 2048; idx += 256) {
            int r = idx >> 4, c4 = (idx & 15) << 2;
            float4 kv = *(const float4*)(gk + (size_t)r * DD + c4);
            float* dk = sK + r * SKl + c4;
            dk[0] = kv.x; dk[1] = kv.y; dk[2] = kv.z; dk[3] = kv.w;
            float4 vv = *(const float4*)(gv + (size_t)r * DD + c4);
            *(float4*)(sV + r * SVl + c4) = vv;
        }
        const int rb0 = 895 + j0 - i0;
        for (int idx = tid; idx < 255 * 16; idx += 256) {
            int li = idx >> 4, c4 = (idx & 15) << 2;
            int r = rb0 + li;
            float4 ev = make_float4(0.f, 0.f, 0.f, 0.f);
            if (r >= 0) ev = *(const float4*)(E + (size_t)r * HDp + c4);
            float* de = sEP + li * SEl + c4;
            de[0] = ev.x; de[1] = ev.y; de[2] = ev.z; de[3] = ev.w;
        }
        __syncthreads();

        float acc[8][8];
        #pragma unroll
        for (int ii = 0; ii < 8; ii++)
            #pragma unroll
            for (int jj = 0; jj < 8; jj++) acc[ii][jj] = 0.f;

        #pragma unroll 2
        for (int d = 0; d < 64; d++) {
            float qf[8], kf[8], ef[15];
            #pragma unroll
            for (int ii = 0; ii < 8; ii++) qf[ii] = bq[ii * (16 * SQl) + d];
            #pragma unroll
            for (int jj = 0; jj < 8; jj++) kf[jj] = bk[jj * (16 * SKl) + d];
            #pragma unroll
            for (int t = 0; t < 15; t++)  ef[t]  = be[t * (16 * SEl) + d];
            #pragma unroll
            for (int ii = 0; ii < 8; ii++)
                #pragma unroll
                for (int jj = 0; jj < 8; jj++)
                    acc[ii][jj] = fmaf(qf[ii], kf[jj] + ef[jj - ii + 7], acc[ii][jj]);
        }

        #pragma unroll
        for (int ii = 0; ii < 8; ii++) {
            float rmax = acc[ii][0];
            #pragma unroll
            for (int jj = 1; jj < 8; jj++) rmax = fmaxf(rmax, acc[ii][jj]);
            #pragma unroll
            for (int off = 8; off >= 1; off >>= 1)
                rmax = fmaxf(rmax, __shfl_xor_sync(0xffffffffu, rmax, off));
            float mnew = fmaxf(mrow[ii], rmax);
            float corr = __expf(mrow[ii] - mnew);
            float rs = 0.f;
            #pragma unroll
            for (int jj = 0; jj < 8; jj++) {
                float p = __expf(acc[ii][jj] - mnew);
                acc[ii][jj] = p;
                rs += p;
            }
            #pragma unroll
            for (int off = 8; off >= 1; off >>= 1)
                rs += __shfl_xor_sync(0xffffffffu, rs, off);
            lrow[ii] = lrow[ii] * corr + rs;
            mrow[ii] = mnew;
            #pragma unroll
            for (int dd = 0; dd < 4; dd++) o[ii][dd] *= corr;
        }
        __syncthreads();

        #pragma unroll
        for (int ii = 0; ii < 8; ii++)
            #pragma unroll
            for (int jj = 0; jj < 8; jj++)
                bpw[ii * (16 * SPl) + jj * 16] = acc[ii][jj];
        __syncthreads();

        #pragma unroll 2
        for (int j = 0; j < 128; j++) {
            float pf[8];
            #pragma unroll
            for (int ii = 0; ii < 8; ii++) pf[ii] = bpr[ii * (16 * SPl) + j];
            float4 vv = *(const float4*)(bv + j * SVl);
            #pragma unroll
            for (int ii = 0; ii < 8; ii++) {
                o[ii][0] = fmaf(pf[ii], vv.x, o[ii][0]);
                o[ii][1] = fmaf(pf[ii], vv.y, o[ii][1]);
                o[ii][2] = fmaf(pf[ii], vv.z, o[ii][2]);
                o[ii][3] = fmaf(pf[ii], vv.w, o[ii][3]);
            }
        }
    }

    float* gc = ctx + ((size_t)(b * LL + i0)) * DD + h * HDp + tx * 4;
    #pragma unroll
    for (int ii = 0; ii < 8; ii++) {
        float inv = 1.f / lrow[ii];
        float4 r;
        r.x = o[ii][0] * inv; r.y = o[ii][1] * inv;
        r.z = o[ii][2] * inv; r.w = o[ii][3] * inv;
        *(float4*)(gc + (size_t)(ty + 16 * ii) * DD) = r;
    }
}

// ---------------------------------------------------------------------------
extern "C" void kernel_launch(void* const* d_in, const int* in_sizes, int n_in,
                              void* d_out, int out_size)
{
    const float* x  = (const float*)d_in[0];
    const float* Wq = (const float*)d_in[1];
    const float* bq = (const float*)d_in[2];
    const float* Wk = (const float*)d_in[3];
    const float* bk = (const float*)d_in[4];
    const float* Wv = (const float*)d_in[5];
    const float* bv = (const float*)d_in[6];
    const float* Wo = (const float*)d_in[7];
    const float* bo = (const float*)d_in[8];
    const float* E  = (const float*)d_in[9];
    float* out = (float*)d_out;

    float *q, *k, *v, *ctx;
    cudaGetSymbolAddress((void**)&q,   g_q);
    cudaGetSymbolAddress((void**)&k,   g_k);
    cudaGetSymbolAddress((void**)&v,   g_v);
    cudaGetSymbolAddress((void**)&ctx, g_ctx);

    cudaFuncSetAttribute(gemm_tc_kernel,
                         cudaFuncAttributeMaxDynamicSharedMemorySize, GEMM_SMEM);
    cudaFuncSetAttribute(attn_kernel,
                         cudaFuncAttributeMaxDynamicSharedMemorySize, ATT_SMEM);

    // 1) Fused QKV projections (mma.sync bf16 hi/lo split)
    gemm_tc_kernel<<<dim3(DD/128, MM/128, 3), 256, GEMM_SMEM>>>(
        x, Wq, Wk, Wv, bq, bk, bv, q, k, v, MM, DD, DD);

    // 2) Fused rel-pos flash attention
    attn_kernel<<<dim3(LL/128, HH, Bb), 256, ATT_SMEM>>>(q, k, v, E, ctx);

    // 3) Output projection
    gemm_tc_kernel<<<dim3(DD/128, MM/128, 1), 256, GEMM_SMEM>>>(
        ctx, Wo, Wo, Wo, bo, bo, bo, out, out, out, MM, DD, DD);
}

// round 5
// speedup vs baseline: 1.9843x; 1.3167x over previous
#include <cuda_runtime.h>
#include <cuda_bf16.h>
#include <math.h>
#include <cstdint>

#define Bb   2
#define LL   1024
#define DD   1024
#define HH   16
#define HDp  64
#define MM   (Bb * LL)
#define NE   (2 * LL - 1)   // 2047

typedef __nv_bfloat16 bf16;

// Scratch (allocation-free rule: device globals)
__device__ bf16 g_xhi[MM * DD],  g_xlo[MM * DD];
__device__ bf16 g_wqh[DD * DD],  g_wql[DD * DD];
__device__ bf16 g_wkh[DD * DD],  g_wkl[DD * DD];
__device__ bf16 g_wvh[DD * DD],  g_wvl[DD * DD];
__device__ bf16 g_woh[DD * DD],  g_wol[DD * DD];
__device__ bf16 g_qhi[MM * DD],  g_qlo[MM * DD];
__device__ bf16 g_khi[MM * DD],  g_klo[MM * DD];
__device__ bf16 g_vhi[MM * DD],  g_vlo[MM * DD];
__device__ bf16 g_ehi[NE * HDp], g_elo[NE * HDp];
__device__ bf16 g_chi[MM * DD],  g_clo[MM * DD];

// ===========================================================================
// Helpers (sm_80+ ISA; proven on this toolchain in R4)
// ===========================================================================
__device__ __forceinline__ uint32_t smem_u32(const void* p) {
    uint32_t a;
    asm("{ .reg .u64 t; cvta.to.shared.u64 t, %1; cvt.u32.u64 %0, t; }"
        : "=r"(a) : "l"(p));
    return a;
}
__device__ __forceinline__ void ldsm_x4(uint32_t addr, uint32_t r[4]) {
    asm volatile("ldmatrix.sync.aligned.m8n8.x4.shared.b16 {%0,%1,%2,%3}, [%4];"
                 : "=r"(r[0]), "=r"(r[1]), "=r"(r[2]), "=r"(r[3]) : "r"(addr));
}
__device__ __forceinline__ void mma_bf16(float c[4], const uint32_t a[4],
                                         uint32_t b0, uint32_t b1) {
    asm volatile(
        "mma.sync.aligned.m16n8k16.row.col.f32.bf16.bf16.f32 "
        "{%0,%1,%2,%3}, {%4,%5,%6,%7}, {%8,%9}, {%0,%1,%2,%3};"
        : "+f"(c[0]), "+f"(c[1]), "+f"(c[2]), "+f"(c[3])
        : "r"(a[0]), "r"(a[1]), "r"(a[2]), "r"(a[3]), "r"(b0), "r"(b1));
}
__device__ __forceinline__ uint32_t pack2(bf16 a, bf16 b) {
    return (uint32_t)__bfloat16_as_ushort(a) | ((uint32_t)__bfloat16_as_ushort(b) << 16);
}
__device__ __forceinline__ void split_pair(float a, float b, uint32_t& hi, uint32_t& lo) {
    bf16 ha = __float2bfloat16(a), hb = __float2bfloat16(b);
    hi = pack2(ha, hb);
    lo = pack2(__float2bfloat16(a - __bfloat162float(ha)),
               __float2bfloat16(b - __bfloat162float(hb)));
}

// ===========================================================================
// fp32 -> bf16 hi/lo split (elementwise)
// ===========================================================================
__global__ void cvt_split_kernel(const float* __restrict__ s,
                                 bf16* __restrict__ hi, bf16* __restrict__ lo, int n)
{
    int i = (blockIdx.x * 256 + threadIdx.x) * 4;
    if (i >= n) return;
    float4 v = *(const float4*)(s + i);
    uint32_t h0, l0, h1, l1;
    split_pair(v.x, v.y, h0, l0);
    split_pair(v.z, v.w, h1, l1);
    *(uint2*)(hi + i) = make_uint2(h0, h1);
    *(uint2*)(lo + i) = make_uint2(l0, l1);
}

// ===========================================================================
// Tensor-core GEMM: C = A(MxK) @ W(NxK)^T + bias, pre-split bf16 inputs.
// 128x128 CTA tile, 8 warps (2m x 4n). K chunks of 64.
// Epilogue: fp32 out (cf != null) or bf16 hi/lo split out with scale.
// ===========================================================================
#define GSA     144
#define GTILE_B (128 * GSA)
#define OFF_AHI 0
#define OFF_ALO GTILE_B
#define OFF_BHI (2 * GTILE_B)
#define OFF_BLO (3 * GTILE_B)
#define GEMM_SMEM (4 * GTILE_B)

__global__ __launch_bounds__(256, 2)
void gemm_tc2_kernel(const bf16* __restrict__ ahi, const bf16* __restrict__ alo,
                     const bf16* __restrict__ w0h, const bf16* __restrict__ w0l,
                     const bf16* __restrict__ w1h, const bf16* __restrict__ w1l,
                     const bf16* __restrict__ w2h, const bf16* __restrict__ w2l,
                     const float* __restrict__ b0, const float* __restrict__ b1,
                     const float* __restrict__ b2,
                     bf16* c0h, bf16* c0l, bf16* c1h, bf16* c1l,
                     bf16* c2h, bf16* c2l,
                     float* cf, float scale0, int M, int N, int K)
{
    const int z = blockIdx.z;
    const bf16* wh   = (z == 0) ? w0h : (z == 1 ? w1h : w2h);
    const bf16* wl   = (z == 0) ? w0l : (z == 1 ? w1l : w2l);
    const float* bias = (z == 0) ? b0 : (z == 1 ? b1 : b2);
    bf16* chi = (z == 0) ? c0h : (z == 1 ? c1h : c2h);
    bf16* clo = (z == 0) ? c0l : (z == 1 ? c1l : c2l);
    const float scale = (z == 0) ? scale0 : 1.0f;

    extern __shared__ char sm[];
    const uint32_t sbase = smem_u32(sm);

    const int tid  = threadIdx.x;
    const int lane = tid & 31;
    const int wid  = tid >> 5;
    const int wm   = wid & 1;
    const int wn   = wid >> 1;
    const int bm   = blockIdx.y * 128;
    const int bn   = blockIdx.x * 128;

    float acc[4][4][4];
    #pragma unroll
    for (int i = 0; i < 4; i++)
        #pragma unroll
        for (int j = 0; j < 4; j++)
            #pragma unroll
            for (int r = 0; r < 4; r++) acc[i][j][r] = 0.f;

    const int frow = tid >> 1;
    const int fcol = (tid & 1) * 32;
    const bf16* pah = ahi + (size_t)(bm + frow) * K + fcol;
    const bf16* pal = alo + (size_t)(bm + frow) * K + fcol;
    const bf16* pwh = wh  + (size_t)(bn + frow) * K + fcol;
    const bf16* pwl = wl  + (size_t)(bn + frow) * K + fcol;
    char* frowp = sm + frow * GSA + fcol * 2;

    const int lr   = lane & 15;
    const int lc16 = (lane >> 4) * 16;
    const uint32_t a_lane = sbase + (uint32_t)((wm * 64 + lr) * GSA + lc16);
    const uint32_t b_lane = sbase + (uint32_t)((wn * 32 + lr) * GSA + lc16);

    for (int c = 0; c < K / 64; c++) {
        const int kb = c * 64;
        __syncthreads();
        #pragma unroll
        for (int g = 0; g < 4; g++) {
            *(uint4*)(frowp + OFF_AHI + g * 16) = *(const uint4*)(pah + kb + g * 8);
            *(uint4*)(frowp + OFF_ALO + g * 16) = *(const uint4*)(pal + kb + g * 8);
            *(uint4*)(frowp + OFF_BHI + g * 16) = *(const uint4*)(pwh + kb + g * 8);
            *(uint4*)(frowp + OFF_BLO + g * 16) = *(const uint4*)(pwl + kb + g * 8);
        }
        __syncthreads();

        #pragma unroll
        for (int ks = 0; ks < 4; ks++) {
            const uint32_t cb = (uint32_t)(ks * 32);
            uint32_t ah[4][4], al[4][4];
            #pragma unroll
            for (int mi = 0; mi < 4; mi++) {
                ldsm_x4(a_lane + OFF_AHI + mi * (16 * GSA) + cb, ah[mi]);
                ldsm_x4(a_lane + OFF_ALO + mi * (16 * GSA) + cb, al[mi]);
            }
            #pragma unroll
            for (int nb = 0; nb < 2; nb++) {
                uint32_t bh[4], bl[4];
                ldsm_x4(b_lane + OFF_BHI + nb * (16 * GSA) + cb, bh);
                ldsm_x4(b_lane + OFF_BLO + nb * (16 * GSA) + cb, bl);
                #pragma unroll
                for (int mi = 0; mi < 4; mi++) {
                    mma_bf16(acc[mi][2*nb],   ah[mi], bh[0], bh[2]);
                    mma_bf16(acc[mi][2*nb],   ah[mi], bl[0], bl[2]);
                    mma_bf16(acc[mi][2*nb],   al[mi], bh[0], bh[2]);
                    mma_bf16(acc[mi][2*nb+1], ah[mi], bh[1], bh[3]);
                    mma_bf16(acc[mi][2*nb+1], ah[mi], bl[1], bl[3]);
                    mma_bf16(acc[mi][2*nb+1], al[mi], bh[1], bh[3]);
                }
            }
        }
    }

    const int ql = lane >> 2;
    const int rl = (lane & 3) * 2;
    #pragma unroll
    for (int mi = 0; mi < 4; mi++) {
        const int m = bm + wm * 64 + mi * 16 + ql;
        #pragma unroll
        for (int nj = 0; nj < 4; nj++) {
            const int n = bn + wn * 32 + nj * 8 + rl;
            const float bz0 = bias[n], bz1 = bias[n + 1];
            if (cf) {
                float2 v;
                v.x = acc[mi][nj][0] + bz0; v.y = acc[mi][nj][1] + bz1;
                *(float2*)(cf + (size_t)m * N + n) = v;
                v.x = acc[mi][nj][2] + bz0; v.y = acc[mi][nj][3] + bz1;
                *(float2*)(cf + (size_t)(m + 8) * N + n) = v;
            } else {
                uint32_t h, l;
                split_pair((acc[mi][nj][0] + bz0) * scale,
                           (acc[mi][nj][1] + bz1) * scale, h, l);
                *(uint32_t*)(chi + (size_t)m * N + n) = h;
                *(uint32_t*)(clo + (size_t)m * N + n) = l;
                split_pair((acc[mi][nj][2] + bz0) * scale,
                           (acc[mi][nj][3] + bz1) * scale, h, l);
                *(uint32_t*)(chi + (size_t)(m + 8) * N + n) = h;
                *(uint32_t*)(clo + (size_t)(m + 8) * N + n) = l;
            }
        }
    }
}

// ===========================================================================
// Tensor-core flash attention with fused rel-pos band.
// rel[i,j] = q_i . E[j - i + L - 2]  (E row -1 => 0)
// CTA: 128 queries x 128-key tiles, 8 warps, each warp owns 16 query rows.
// Band: R = Q . E_band^T (128 x 256), scattered into sS via j = li + i - 127.
// ===========================================================================
#define AKS 144                          // K/E row stride bytes (64 bf16 + pad)
#define AVS 272                          // V^T row stride bytes (128 bf16 + pad)
#define A_KHI 0
#define A_KLO 18432
#define A_VHI 36864
#define A_VLO 54272
#define A_EHI 71680
#define A_ELO 108544
#define A_S   145408                     // fp32 S tile, 128 x 132
#define ATT_SMEM 212992

__global__ __launch_bounds__(256, 1)
void attn_tc_kernel(const bf16* __restrict__ qhi, const bf16* __restrict__ qlo,
                    const bf16* __restrict__ khi, const bf16* __restrict__ klo,
                    const bf16* __restrict__ vhi, const bf16* __restrict__ vlo,
                    const bf16* __restrict__ ehi, const bf16* __restrict__ elo,
                    bf16* __restrict__ chi, bf16* __restrict__ clo)
{
    extern __shared__ char sm[];
    const uint32_t sb = smem_u32(sm);
    float* sS = (float*)(sm + A_S);

    const int tid  = threadIdx.x;
    const int lane = tid & 31;
    const int w    = tid >> 5;
    const int g    = lane >> 2;
    const int rl   = lane & 3;
    const int i0   = blockIdx.x * 128;
    const int h    = blockIdx.y;
    const int b    = blockIdx.z;
    const size_t tokq = (size_t)(b * LL + i0);

    // ---- stage Q (hi/lo) into the sS region, then grab A-frags ----
    {
        const int r = tid >> 1, ch = (tid & 1) * 32;
        const bf16* ph = qhi + (tokq + r) * DD + h * HDp + ch;
        const bf16* pl = qlo + (tokq + r) * DD + h * HDp + ch;
        char* dh = sm + A_S + r * AKS + ch * 2;
        char* dl = sm + A_S + 18432 + r * AKS + ch * 2;
        #pragma unroll
        for (int g2 = 0; g2 < 4; g2++) {
            *(uint4*)(dh + g2 * 16) = *(const uint4*)(ph + g2 * 8);
            *(uint4*)(dl + g2 * 16) = *(const uint4*)(pl + g2 * 8);
        }
    }
    __syncthreads();
    uint32_t qh[4][4], ql4[4][4];
    {
        const uint32_t aq = sb + A_S + (uint32_t)((w * 16 + (lane & 15)) * AKS + (lane >> 4) * 16);
        #pragma unroll
        for (int ks = 0; ks < 4; ks++) {
            ldsm_x4(aq + ks * 32, qh[ks]);
            ldsm_x4(aq + 18432 + ks * 32, ql4[ks]);
        }
    }

    float m0 = -1e30f, m1 = -1e30f, den0 = 0.f, den1 = 0.f;
    float o[8][4];
    #pragma unroll
    for (int i = 0; i < 8; i++)
        #pragma unroll
        for (int r = 0; r < 4; r++) o[i][r] = 0.f;

    const int r0 = w * 16 + g, r1 = r0 + 8;

    for (int jt = 0; jt < LL / 128; jt++) {
        const int j0 = jt * 128;
        __syncthreads();

        // ---- load K hi/lo ----
        {
            const int r = tid >> 1, ch = (tid & 1) * 32;
            const bf16* ph = khi + ((size_t)(b * LL + j0 + r)) * DD + h * HDp + ch;
            const bf16* pl = klo + ((size_t)(b * LL + j0 + r)) * DD + h * HDp + ch;
            char* dh = sm + A_KHI + r * AKS + ch * 2;
            char* dl = sm + A_KLO + r * AKS + ch * 2;
            #pragma unroll
            for (int g2 = 0; g2 < 4; g2++) {
                *(uint4*)(dh + g2 * 16) = *(const uint4*)(ph + g2 * 8);
                *(uint4*)(dl + g2 * 16) = *(const uint4*)(pl + g2 * 8);
            }
        }
        // ---- load V transposed (rows = d, cols = j) ----
        {
            const int j = tid >> 1, ch = (tid & 1) * 32;
            const bf16* ph = vhi + ((size_t)(b * LL + j0 + j)) * DD + h * HDp + ch;
            const bf16* pl = vlo + ((size_t)(b * LL + j0 + j)) * DD + h * HDp + ch;
            unsigned short* sh = (unsigned short*)(sm + A_VHI);
            unsigned short* sl = (unsigned short*)(sm + A_VLO);
            #pragma unroll
            for (int g2 = 0; g2 < 4; g2++) {
                uint4 uh = *(const uint4*)(ph + g2 * 8);
                uint4 ul = *(const uint4*)(pl + g2 * 8);
                const unsigned short* xh = (const unsigned short*)&uh;
                const unsigned short* xl = (const unsigned short*)&ul;
                #pragma unroll
                for (int e = 0; e < 8; e++) {
                    const int d = ch + g2 * 8 + e;
                    sh[d * (AVS / 2) + j] = xh[e];
                    sl[d * (AVS / 2) + j] = xl[e];
                }
            }
        }
        // ---- load E band (256 rows, zero-filled below r=0) ----
        {
            const int rb0 = 895 + j0 - i0;
            #pragma unroll
            for (int pass = 0; pass < 2; pass++) {
                const int idx = tid + pass * 256;
                const int li = idx >> 1, ch = (idx & 1) * 32;
                const int r = rb0 + li;
                char* dh = sm + A_EHI + li * AKS + ch * 2;
                char* dl = sm + A_ELO + li * AKS + ch * 2;
                if (r >= 0 && r < NE) {
                    const bf16* ph = ehi + (size_t)r * HDp + ch;
                    const bf16* pl = elo + (size_t)r * HDp + ch;
                    #pragma unroll
                    for (int g2 = 0; g2 < 4; g2++) {
                        *(uint4*)(dh + g2 * 16) = *(const uint4*)(ph + g2 * 8);
                        *(uint4*)(dl + g2 * 16) = *(const uint4*)(pl + g2 * 8);
                    }
                } else {
                    const uint4 z = make_uint4(0, 0, 0, 0);
                    #pragma unroll
                    for (int g2 = 0; g2 < 4; g2++) {
                        *(uint4*)(dh + g2 * 16) = z;
                        *(uint4*)(dl + g2 * 16) = z;
                    }
                }
            }
        }
        __syncthreads();

        // ---- band mma: R = Q . E^T, scatter into sS (own rows only) ----
        {
            const uint32_t be = sb + A_EHI + (uint32_t)((lane & 15) * AKS + (lane >> 4) * 16);
            #pragma unroll 4
            for (int eb = 0; eb < 16; eb++) {
                float ba[2][4] = {{0, 0, 0, 0}, {0, 0, 0, 0}};
                #pragma unroll
                for (int ks = 0; ks < 4; ks++) {
                    uint32_t eh[4], el[4];
                    ldsm_x4(be + eb * (16 * AKS) + ks * 32, eh);
                    ldsm_x4(be + (A_ELO - A_EHI) + eb * (16 * AKS) + ks * 32, el);
                    mma_bf16(ba[0], qh[ks],  eh[0], eh[2]);
                    mma_bf16(ba[0], qh[ks],  el[0], el[2]);
                    mma_bf16(ba[0], ql4[ks], eh[0], eh[2]);
                    mma_bf16(ba[1], qh[ks],  eh[1], eh[3]);
                    mma_bf16(ba[1], qh[ks],  el[1], el[3]);
                    mma_bf16(ba[1], ql4[ks], eh[1], eh[3]);
                }
                #pragma unroll
                for (int hf = 0; hf < 2; hf++) {
                    const int li = (eb * 2 + hf) * 8 + rl * 2;
                    int jl;
                    jl = li + r0 - 127;     if (jl >= 0 && jl < 128) sS[r0 * 132 + jl] = ba[hf][0];
                    jl = li + 1 + r0 - 127; if (jl >= 0 && jl < 128) sS[r0 * 132 + jl] = ba[hf][1];
                    jl = li + r1 - 127;     if (jl >= 0 && jl < 128) sS[r1 * 132 + jl] = ba[hf][2];
                    jl = li + 1 + r1 - 127; if (jl >= 0 && jl < 128) sS[r1 * 132 + jl] = ba[hf][3];
                }
            }
        }

        // ---- QK mma ----
        float acc[16][4];
        #pragma unroll
        for (int i = 0; i < 16; i++)
            #pragma unroll
            for (int r = 0; r < 4; r++) acc[i][r] = 0.f;
        {
            const uint32_t bk = sb + A_KHI + (uint32_t)((lane & 15) * AKS + (lane >> 4) * 16);
            #pragma unroll 4
            for (int nb = 0; nb < 8; nb++) {
                #pragma unroll
                for (int ks = 0; ks < 4; ks++) {
                    uint32_t kh[4], kl[4];
                    ldsm_x4(bk + nb * (16 * AKS) + ks * 32, kh);
                    ldsm_x4(bk + (A_KLO - A_KHI) + nb * (16 * AKS) + ks * 32, kl);
                    mma_bf16(acc[2*nb],   qh[ks],  kh[0], kh[2]);
                    mma_bf16(acc[2*nb],   qh[ks],  kl[0], kl[2]);
                    mma_bf16(acc[2*nb],   ql4[ks], kh[0], kh[2]);
                    mma_bf16(acc[2*nb+1], qh[ks],  kh[1], kh[3]);
                    mma_bf16(acc[2*nb+1], qh[ks],  kl[1], kl[3]);
                    mma_bf16(acc[2*nb+1], ql4[ks], kh[1], kh[3]);
                }
            }
        }

        // ---- add band, online softmax ----
        {
            const float* s0 = sS + r0 * 132;
            const float* s1 = sS + r1 * 132;
            #pragma unroll
            for (int nb8 = 0; nb8 < 16; nb8++) {
                const int c = nb8 * 8 + rl * 2;
                acc[nb8][0] += s0[c];     acc[nb8][1] += s0[c + 1];
                acc[nb8][2] += s1[c];     acc[nb8][3] += s1[c + 1];
            }
            float mx0 = -1e30f, mx1 = -1e30f;
            #pragma unroll
            for (int nb8 = 0; nb8 < 16; nb8++) {
                mx0 = fmaxf(mx0, fmaxf(acc[nb8][0], acc[nb8][1]));
                mx1 = fmaxf(mx1, fmaxf(acc[nb8][2], acc[nb8][3]));
            }
            mx0 = fmaxf(mx0, __shfl_xor_sync(0xffffffffu, mx0, 1));
            mx0 = fmaxf(mx0, __shfl_xor_sync(0xffffffffu, mx0, 2));
            mx1 = fmaxf(mx1, __shfl_xor_sync(0xffffffffu, mx1, 1));
            mx1 = fmaxf(mx1, __shfl_xor_sync(0xffffffffu, mx1, 2));
            const float nm0 = fmaxf(m0, mx0), nm1 = fmaxf(m1, mx1);
            const float cr0 = __expf(m0 - nm0), cr1 = __expf(m1 - nm1);
            float s0s = 0.f, s1s = 0.f;
            #pragma unroll
            for (int nb8 = 0; nb8 < 16; nb8++) {
                acc[nb8][0] = __expf(acc[nb8][0] - nm0); s0s += acc[nb8][0];
                acc[nb8][1] = __expf(acc[nb8][1] - nm0); s0s += acc[nb8][1];
                acc[nb8][2] = __expf(acc[nb8][2] - nm1); s1s += acc[nb8][2];
                acc[nb8][3] = __expf(acc[nb8][3] - nm1); s1s += acc[nb8][3];
            }
            s0s += __shfl_xor_sync(0xffffffffu, s0s, 1);
            s0s += __shfl_xor_sync(0xffffffffu, s0s, 2);
            s1s += __shfl_xor_sync(0xffffffffu, s1s, 1);
            s1s += __shfl_xor_sync(0xffffffffu, s1s, 2);
            den0 = den0 * cr0 + s0s; den1 = den1 * cr1 + s1s;
            m0 = nm0; m1 = nm1;
            #pragma unroll
            for (int nd = 0; nd < 8; nd++) {
                o[nd][0] *= cr0; o[nd][1] *= cr0;
                o[nd][2] *= cr1; o[nd][3] *= cr1;
            }
        }

        // ---- PV mma: O += P . V ----
        {
            const uint32_t bv = sb + A_VHI + (uint32_t)((lane & 15) * AVS + (lane >> 4) * 16);
            #pragma unroll 2
            for (int kb = 0; kb < 8; kb++) {
                uint32_t ph4[4], pl4[4];
                split_pair(acc[2*kb][0],   acc[2*kb][1],   ph4[0], pl4[0]);
                split_pair(acc[2*kb][2],   acc[2*kb][3],   ph4[1], pl4[1]);
                split_pair(acc[2*kb+1][0], acc[2*kb+1][1], ph4[2], pl4[2]);
                split_pair(acc[2*kb+1][2], acc[2*kb+1][3], ph4[3], pl4[3]);
                #pragma unroll
                for (int dn = 0; dn < 4; dn++) {
                    uint32_t vh[4], vl[4];
                    ldsm_x4(bv + dn * (16 * AVS) + kb * 32, vh);
                    ldsm_x4(bv + (A_VLO - A_VHI) + dn * (16 * AVS) + kb * 32, vl);
                    mma_bf16(o[2*dn],   ph4, vh[0], vh[2]);
                    mma_bf16(o[2*dn],   ph4, vl[0], vl[2]);
                    mma_bf16(o[2*dn],   pl4, vh[0], vh[2]);
                    mma_bf16(o[2*dn+1], ph4, vh[1], vh[3]);
                    mma_bf16(o[2*dn+1], ph4, vl[1], vl[3]);
                    mma_bf16(o[2*dn+1], pl4, vh[1], vh[3]);
                }
            }
        }
    }

    // ---- epilogue: normalize, split to bf16 hi/lo ctx ----
    {
        const float inv0 = 1.f / den0, inv1 = 1.f / den1;
        const size_t t0 = tokq + r0, t1 = tokq + r1;
        #pragma unroll
        for (int nd = 0; nd < 8; nd++) {
            const int d = nd * 8 + rl * 2;
            uint32_t hw, lw;
            split_pair(o[nd][0] * inv0, o[nd][1] * inv0, hw, lw);
            *(uint32_t*)(chi + t0 * DD + h * HDp + d) = hw;
            *(uint32_t*)(clo + t0 * DD + h * HDp + d) = lw;
            split_pair(o[nd][2] * inv1, o[nd][3] * inv1, hw, lw);
            *(uint32_t*)(chi + t1 * DD + h * HDp + d) = hw;
            *(uint32_t*)(clo + t1 * DD + h * HDp + d) = lw;
        }
    }
}

// ---------------------------------------------------------------------------
extern "C" void kernel_launch(void* const* d_in, const int* in_sizes, int n_in,
                              void* d_out, int out_size)
{
    const float* x  = (const float*)d_in[0];
    const float* Wq = (const float*)d_in[1];
    const float* bq = (const float*)d_in[2];
    const float* Wk = (const float*)d_in[3];
    const float* bk = (const float*)d_in[4];
    const float* Wv = (const float*)d_in[5];
    const float* bv = (const float*)d_in[6];
    const float* Wo = (const float*)d_in[7];
    const float* bo = (const float*)d_in[8];
    const float* E  = (const float*)d_in[9];
    float* out = (float*)d_out;

    bf16 *xhi, *xlo, *wqh, *wql, *wkh, *wkl, *wvh, *wvl, *woh, *wol;
    bf16 *qhi, *qlo, *khi, *klo, *vhi, *vlo, *ehi, *elo, *chi, *clo;
    cudaGetSymbolAddress((void**)&xhi, g_xhi); cudaGetSymbolAddress((void**)&xlo, g_xlo);
    cudaGetSymbolAddress((void**)&wqh, g_wqh); cudaGetSymbolAddress((void**)&wql, g_wql);
    cudaGetSymbolAddress((void**)&wkh, g_wkh); cudaGetSymbolAddress((void**)&wkl, g_wkl);
    cudaGetSymbolAddress((void**)&wvh, g_wvh); cudaGetSymbolAddress((void**)&wvl, g_wvl);
    cudaGetSymbolAddress((void**)&woh, g_woh); cudaGetSymbolAddress((void**)&wol, g_wol);
    cudaGetSymbolAddress((void**)&qhi, g_qhi); cudaGetSymbolAddress((void**)&qlo, g_qlo);
    cudaGetSymbolAddress((void**)&khi, g_khi); cudaGetSymbolAddress((void**)&klo, g_klo);
    cudaGetSymbolAddress((void**)&vhi, g_vhi); cudaGetSymbolAddress((void**)&vlo, g_vlo);
    cudaGetSymbolAddress((void**)&ehi, g_ehi); cudaGetSymbolAddress((void**)&elo, g_elo);
    cudaGetSymbolAddress((void**)&chi, g_chi); cudaGetSymbolAddress((void**)&clo, g_clo);

    cudaFuncSetAttribute(gemm_tc2_kernel,
                         cudaFuncAttributeMaxDynamicSharedMemorySize, GEMM_SMEM);
    cudaFuncSetAttribute(attn_tc_kernel,
                         cudaFuncAttributeMaxDynamicSharedMemorySize, ATT_SMEM);

    // 0) split inputs into bf16 hi/lo
    cvt_split_kernel<<<MM * DD / 1024, 256>>>(x,  xhi, xlo, MM * DD);
    cvt_split_kernel<<<DD * DD / 1024, 256>>>(Wq, wqh, wql, DD * DD);
    cvt_split_kernel<<<DD * DD / 1024, 256>>>(Wk, wkh, wkl, DD * DD);
    cvt_split_kernel<<<DD * DD / 1024, 256>>>(Wv, wvh, wvl, DD * DD);
    cvt_split_kernel<<<DD * DD / 1024, 256>>>(Wo, woh, wol, DD * DD);
    cvt_split_kernel<<<(NE * HDp + 1023) / 1024, 256>>>(E, ehi, elo, NE * HDp);

    // 1) fused QKV projections -> bf16 hi/lo q(scaled), k, v
    gemm_tc2_kernel<<<dim3(DD / 128, MM / 128, 3), 256, GEMM_SMEM>>>(
        xhi, xlo, wqh, wql, wkh, wkl, wvh, wvl, bq, bk, bv,
        qhi, qlo, khi, klo, vhi, vlo, nullptr, 0.125f, MM, DD, DD);

    // 2) tensor-core flash attention with rel-pos band
    attn_tc_kernel<<<dim3(LL / 128, HH, Bb), 256, ATT_SMEM>>>(
        qhi, qlo, khi, klo, vhi, vlo, ehi, elo, chi, clo);

    // 3) output projection -> fp32 out
    gemm_tc2_kernel<<<dim3(DD / 128, MM / 128, 1), 256, GEMM_SMEM>>>(
        chi, clo, woh, wol, woh, wol, woh, wol, bo, bo, bo,
        nullptr, nullptr, nullptr, nullptr, nullptr, nullptr,
        out, 1.0f, MM, DD, DD);
}

// round 7
// speedup vs baseline: 2.1809x; 1.0991x over previous
#include <cuda_runtime.h>
#include <cuda_bf16.h>
#include <math.h>
#include <cstdint>

#define Bb   2
#define LL   1024
#define DD   1024
#define HH   16
#define HDp  64
#define MM   (Bb * LL)
#define NE   (2 * LL - 1)   // 2047

typedef __nv_bfloat16 bf16;

// Scratch (allocation-free rule: device globals)
__device__ bf16 g_xhi[MM * DD],  g_xlo[MM * DD];
__device__ bf16 g_wqh[DD * DD],  g_wql[DD * DD];
__device__ bf16 g_wkh[DD * DD],  g_wkl[DD * DD];
__device__ bf16 g_wvh[DD * DD],  g_wvl[DD * DD];
__device__ bf16 g_woh[DD * DD],  g_wol[DD * DD];
__device__ bf16 g_qhi[MM * DD],  g_qlo[MM * DD];
__device__ bf16 g_khi[MM * DD],  g_klo[MM * DD];
__device__ bf16 g_vhi[MM * DD],  g_vlo[MM * DD];
__device__ bf16 g_ehi[NE * HDp], g_elo[NE * HDp];
__device__ bf16 g_chi[MM * DD],  g_clo[MM * DD];

// ===========================================================================
// Helpers (sm_80+ ISA; proven on this toolchain)
// ===========================================================================
__device__ __forceinline__ uint32_t smem_u32(const void* p) {
    uint32_t a;
    asm("{ .reg .u64 t; cvta.to.shared.u64 t, %1; cvt.u32.u64 %0, t; }"
        : "=r"(a) : "l"(p));
    return a;
}
__device__ __forceinline__ void ldsm_x4(uint32_t addr, uint32_t r[4]) {
    asm volatile("ldmatrix.sync.aligned.m8n8.x4.shared.b16 {%0,%1,%2,%3}, [%4];"
                 : "=r"(r[0]), "=r"(r[1]), "=r"(r[2]), "=r"(r[3]) : "r"(addr));
}
__device__ __forceinline__ void ldsm_x4t(uint32_t addr, uint32_t r[4]) {
    asm volatile("ldmatrix.sync.aligned.m8n8.x4.trans.shared.b16 {%0,%1,%2,%3}, [%4];"
                 : "=r"(r[0]), "=r"(r[1]), "=r"(r[2]), "=r"(r[3]) : "r"(addr));
}
__device__ __forceinline__ void mma_bf16(float c[4], const uint32_t a[4],
                                         uint32_t b0, uint32_t b1) {
    asm volatile(
        "mma.sync.aligned.m16n8k16.row.col.f32.bf16.bf16.f32 "
        "{%0,%1,%2,%3}, {%4,%5,%6,%7}, {%8,%9}, {%0,%1,%2,%3};"
        : "+f"(c[0]), "+f"(c[1]), "+f"(c[2]), "+f"(c[3])
        : "r"(a[0]), "r"(a[1]), "r"(a[2]), "r"(a[3]), "r"(b0), "r"(b1));
}
__device__ __forceinline__ void cp16(uint32_t dst, const void* src) {
    asm volatile("cp.async.ca.shared.global [%0], [%1], 16;"
                 :: "r"(dst), "l"(src));
}
__device__ __forceinline__ void cp16z(uint32_t dst, const void* src, bool pred) {
    int sz = pred ? 16 : 0;
    asm volatile("cp.async.ca.shared.global [%0], [%1], 16, %2;"
                 :: "r"(dst), "l"(src), "r"(sz));
}
#define CP_WAIT_ALL() do {                                  \
    asm volatile("cp.async.commit_group;");                 \
    asm volatile("cp.async.wait_group 0;" ::: "memory");    \
} while (0)

__device__ __forceinline__ uint32_t pack2(bf16 a, bf16 b) {
    return (uint32_t)__bfloat16_as_ushort(a) | ((uint32_t)__bfloat16_as_ushort(b) << 16);
}
__device__ __forceinline__ void split_pair(float a, float b, uint32_t& hi, uint32_t& lo) {
    bf16 ha = __float2bfloat16(a), hb = __float2bfloat16(b);
    hi = pack2(ha, hb);
    lo = pack2(__float2bfloat16(a - __bfloat162float(ha)),
               __float2bfloat16(b - __bfloat162float(hb)));
}

// ===========================================================================
// fp32 -> bf16 hi/lo split (elementwise)
// ===========================================================================
__global__ void cvt_split_kernel(const float* __restrict__ s,
                                 bf16* __restrict__ hi, bf16* __restrict__ lo, int n)
{
    int i = (blockIdx.x * 256 + threadIdx.x) * 4;
    if (i >= n) return;
    float4 v = *(const float4*)(s + i);
    uint32_t h0, l0, h1, l1;
    split_pair(v.x, v.y, h0, l0);
    split_pair(v.z, v.w, h1, l1);
    *(uint2*)(hi + i) = make_uint2(h0, h1);
    *(uint2*)(lo + i) = make_uint2(l0, l1);
}

// ===========================================================================
// Tensor-core GEMM: C = A(MxK) @ W(NxK)^T + bias, pre-split bf16 inputs.
// 128x128 CTA tile, 8 warps (2m x 4n). K chunks of 64. cp.async fills.
// ===========================================================================
#define GSA     144
#define GTILE_B (128 * GSA)
#define OFF_AHI 0
#define OFF_ALO GTILE_B
#define OFF_BHI (2 * GTILE_B)
#define OFF_BLO (3 * GTILE_B)
#define GEMM_SMEM (4 * GTILE_B)

__global__ __launch_bounds__(256, 2)
void gemm_tc2_kernel(const bf16* __restrict__ ahi, const bf16* __restrict__ alo,
                     const bf16* __restrict__ w0h, const bf16* __restrict__ w0l,
                     const bf16* __restrict__ w1h, const bf16* __restrict__ w1l,
                     const bf16* __restrict__ w2h, const bf16* __restrict__ w2l,
                     const float* __restrict__ b0, const float* __restrict__ b1,
                     const float* __restrict__ b2,
                     bf16* c0h, bf16* c0l, bf16* c1h, bf16* c1l,
                     bf16* c2h, bf16* c2l,
                     float* cf, float scale0, int M, int N, int K)
{
    const int z = blockIdx.z;
    const bf16* wh   = (z == 0) ? w0h : (z == 1 ? w1h : w2h);
    const bf16* wl   = (z == 0) ? w0l : (z == 1 ? w1l : w2l);
    const float* bias = (z == 0) ? b0 : (z == 1 ? b1 : b2);
    bf16* chi = (z == 0) ? c0h : (z == 1 ? c1h : c2h);
    bf16* clo = (z == 0) ? c0l : (z == 1 ? c1l : c2l);
    const float scale = (z == 0) ? scale0 : 1.0f;

    extern __shared__ char sm[];
    const uint32_t sbase = smem_u32(sm);

    const int tid  = threadIdx.x;
    const int lane = tid & 31;
    const int wid  = tid >> 5;
    const int wm   = wid & 1;
    const int wn   = wid >> 1;
    const int bm   = blockIdx.y * 128;
    const int bn   = blockIdx.x * 128;

    float acc[4][4][4];
    #pragma unroll
    for (int i = 0; i < 4; i++)
        #pragma unroll
        for (int j = 0; j < 4; j++)
            #pragma unroll
            for (int r = 0; r < 4; r++) acc[i][j][r] = 0.f;

    const int frow = tid >> 1;
    const int fcol = (tid & 1) * 32;
    const bf16* pah = ahi + (size_t)(bm + frow) * K + fcol;
    const bf16* pal = alo + (size_t)(bm + frow) * K + fcol;
    const bf16* pwh = wh  + (size_t)(bn + frow) * K + fcol;
    const bf16* pwl = wl  + (size_t)(bn + frow) * K + fcol;
    const uint32_t dstrow = sbase + (uint32_t)(frow * GSA + fcol * 2);

    const int lr   = lane & 15;
    const int lc16 = (lane >> 4) * 16;
    const uint32_t a_lane = sbase + (uint32_t)((wm * 64 + lr) * GSA + lc16);
    const uint32_t b_lane = sbase + (uint32_t)((wn * 32 + lr) * GSA + lc16);

    for (int c = 0; c < K / 64; c++) {
        const int kb = c * 64;
        __syncthreads();
        #pragma unroll
        for (int g = 0; g < 4; g++) {
            cp16(dstrow + OFF_AHI + g * 16, pah + kb + g * 8);
            cp16(dstrow + OFF_ALO + g * 16, pal + kb + g * 8);
            cp16(dstrow + OFF_BHI + g * 16, pwh + kb + g * 8);
            cp16(dstrow + OFF_BLO + g * 16, pwl + kb + g * 8);
        }
        CP_WAIT_ALL();
        __syncthreads();

        #pragma unroll
        for (int ks = 0; ks < 4; ks++) {
            const uint32_t cb = (uint32_t)(ks * 32);
            uint32_t ah[4][4], al[4][4];
            #pragma unroll
            for (int mi = 0; mi < 4; mi++) {
                ldsm_x4(a_lane + OFF_AHI + mi * (16 * GSA) + cb, ah[mi]);
                ldsm_x4(a_lane + OFF_ALO + mi * (16 * GSA) + cb, al[mi]);
            }
            #pragma unroll
            for (int nb = 0; nb < 2; nb++) {
                uint32_t bh[4], bl[4];
                ldsm_x4(b_lane + OFF_BHI + nb * (16 * GSA) + cb, bh);
                ldsm_x4(b_lane + OFF_BLO + nb * (16 * GSA) + cb, bl);
                #pragma unroll
                for (int mi = 0; mi < 4; mi++) {
                    mma_bf16(acc[mi][2*nb],   ah[mi], bh[0], bh[2]);
                    mma_bf16(acc[mi][2*nb],   ah[mi], bl[0], bl[2]);
                    mma_bf16(acc[mi][2*nb],   al[mi], bh[0], bh[2]);
                    mma_bf16(acc[mi][2*nb+1], ah[mi], bh[1], bh[3]);
                    mma_bf16(acc[mi][2*nb+1], ah[mi], bl[1], bl[3]);
                    mma_bf16(acc[mi][2*nb+1], al[mi], bh[1], bh[3]);
                }
            }
        }
    }

    const int ql = lane >> 2;
    const int rl = (lane & 3) * 2;
    #pragma unroll
    for (int mi = 0; mi < 4; mi++) {
        const int m = bm + wm * 64 + mi * 16 + ql;
        #pragma unroll
        for (int nj = 0; nj < 4; nj++) {
            const int n = bn + wn * 32 + nj * 8 + rl;
            const float bz0 = bias[n], bz1 = bias[n + 1];
            if (cf) {
                float2 v;
                v.x = acc[mi][nj][0] + bz0; v.y = acc[mi][nj][1] + bz1;
                *(float2*)(cf + (size_t)m * N + n) = v;
                v.x = acc[mi][nj][2] + bz0; v.y = acc[mi][nj][3] + bz1;
                *(float2*)(cf + (size_t)(m + 8) * N + n) = v;
            } else {
                uint32_t h, l;
                split_pair((acc[mi][nj][0] + bz0) * scale,
                           (acc[mi][nj][1] + bz1) * scale, h, l);
                *(uint32_t*)(chi + (size_t)m * N + n) = h;
                *(uint32_t*)(clo + (size_t)m * N + n) = l;
                split_pair((acc[mi][nj][2] + bz0) * scale,
                           (acc[mi][nj][3] + bz1) * scale, h, l);
                *(uint32_t*)(chi + (size_t)(m + 8) * N + n) = h;
                *(uint32_t*)(clo + (size_t)(m + 8) * N + n) = l;
            }
        }
    }
}

// ===========================================================================
// Tensor-core flash attention with fused rel-pos band.
// rel[i,j] = q_i . E[j - i + L - 2]  (E row -1 => 0)
// 128 q x 128 k tiles, 8 warps each owning 16 q-rows.
// Band: warp w only computes eb blocks [7-w, 15-w] (exact diagonal coverage),
// full 3-term hi/lo split (E hi AND lo). V row-major, PV via ldmatrix.trans.
// ===========================================================================
#define AKS 144
#define A_KHI 0
#define A_KLO 18432
#define A_VHI 36864
#define A_VLO 55296
#define A_EHI 73728                       // 256 rows x 144 B = 36864
#define A_ELO 110592
#define A_S   147456                      // fp32 S tile 128 x 132 (67584 B)
#define ATT_SMEM (A_S + 128 * 132 * 4)    // 215040 B

__global__ __launch_bounds__(256, 1)
void attn_tc_kernel(const bf16* __restrict__ qhi, const bf16* __restrict__ qlo,
                    const bf16* __restrict__ khi, const bf16* __restrict__ klo,
                    const bf16* __restrict__ vhi, const bf16* __restrict__ vlo,
                    const bf16* __restrict__ ehi, const bf16* __restrict__ elo,
                    bf16* __restrict__ chi, bf16* __restrict__ clo)
{
    extern __shared__ char sm[];
    const uint32_t sb = smem_u32(sm);
    float* sS = (float*)(sm + A_S);

    const int tid  = threadIdx.x;
    const int lane = tid & 31;
    const int w    = tid >> 5;
    const int g    = lane >> 2;
    const int rl   = lane & 3;
    const int i0   = blockIdx.x * 128;
    const int h    = blockIdx.y;
    const int b    = blockIdx.z;
    const size_t tokq = (size_t)(b * LL + i0);

    // ---- stage Q (hi/lo) into S region, grab A-frags ----
    {
        const int r = tid >> 1, ch = (tid & 1) * 32;
        const bf16* ph = qhi + (tokq + r) * DD + h * HDp + ch;
        const bf16* pl = qlo + (tokq + r) * DD + h * HDp + ch;
        const uint32_t dh = sb + A_S + (uint32_t)(r * AKS + ch * 2);
        #pragma unroll
        for (int g2 = 0; g2 < 4; g2++) {
            cp16(dh + g2 * 16,         ph + g2 * 8);
            cp16(dh + 18432 + g2 * 16, pl + g2 * 8);
        }
        CP_WAIT_ALL();
    }
    __syncthreads();
    uint32_t qh[4][4], ql4[4][4];
    {
        const uint32_t aq = sb + A_S + (uint32_t)((w * 16 + (lane & 15)) * AKS + (lane >> 4) * 16);
        #pragma unroll
        for (int ks = 0; ks < 4; ks++) {
            ldsm_x4(aq + ks * 32, qh[ks]);
            ldsm_x4(aq + 18432 + ks * 32, ql4[ks]);
        }
    }

    float m0 = -1e30f, m1 = -1e30f, den0 = 0.f, den1 = 0.f;
    float o[8][4];
    #pragma unroll
    for (int i = 0; i < 8; i++)
        #pragma unroll
        for (int r = 0; r < 4; r++) o[i][r] = 0.f;

    const int r0 = w * 16 + g, r1 = r0 + 8;

    for (int jt = 0; jt < LL / 128; jt++) {
        const int j0 = jt * 128;
        __syncthreads();   // prior tile's K/V/E reads complete

        // ---- async loads: K hi/lo, V hi/lo (row-major), E hi/lo band ----
        {
            const int r = tid >> 1, ch = (tid & 1) * 32;
            const size_t gofs = ((size_t)(b * LL + j0 + r)) * DD + h * HDp + ch;
            const uint32_t drow = (uint32_t)(r * AKS + ch * 2);
            #pragma unroll
            for (int g2 = 0; g2 < 4; g2++) {
                cp16(sb + A_KHI + drow + g2 * 16, khi + gofs + g2 * 8);
                cp16(sb + A_KLO + drow + g2 * 16, klo + gofs + g2 * 8);
                cp16(sb + A_VHI + drow + g2 * 16, vhi + gofs + g2 * 8);
                cp16(sb + A_VLO + drow + g2 * 16, vlo + gofs + g2 * 8);
            }
        }
        {
            const int rb0 = 895 + j0 - i0;
            #pragma unroll
            for (int p = 0; p < 8; p++) {
                const int idx = tid + p * 256;       // 2048 slots: 256 rows x 8 x16B
                const int li = idx >> 3, gcol = (idx & 7) * 8;
                const int r = rb0 + li;
                const int rc = (r < 0) ? 0 : r;
                const bool ok = (r >= 0);
                const uint32_t doff = (uint32_t)(li * AKS + gcol * 2);
                cp16z(sb + A_EHI + doff, ehi + (size_t)rc * HDp + gcol, ok);
                cp16z(sb + A_ELO + doff, elo + (size_t)rc * HDp + gcol, ok);
            }
        }
        CP_WAIT_ALL();
        __syncthreads();

        // ---- band mma: R = Q . E^T on warp's needed eb range, scatter ----
        {
            const uint32_t be = sb + A_EHI + (uint32_t)((lane & 15) * AKS + (lane >> 4) * 16);
            #pragma unroll
            for (int eb = 0; eb < 16; eb++) {
                if (eb < 7 - w || eb > 15 - w) continue;
                float ba[2][4] = {{0, 0, 0, 0}, {0, 0, 0, 0}};
                #pragma unroll
                for (int ks = 0; ks < 4; ks++) {
                    uint32_t eh[4], el[4];
                    ldsm_x4(be + eb * (16 * AKS) + ks * 32, eh);
                    ldsm_x4(be + (A_ELO - A_EHI) + eb * (16 * AKS) + ks * 32, el);
                    mma_bf16(ba[0], qh[ks],  eh[0], eh[2]);
                    mma_bf16(ba[0], qh[ks],  el[0], el[2]);
                    mma_bf16(ba[0], ql4[ks], eh[0], eh[2]);
                    mma_bf16(ba[1], qh[ks],  eh[1], eh[3]);
                    mma_bf16(ba[1], qh[ks],  el[1], el[3]);
                    mma_bf16(ba[1], ql4[ks], eh[1], eh[3]);
                }
                #pragma unroll
                for (int hf = 0; hf < 2; hf++) {
                    const int li = (eb * 2 + hf) * 8 + rl * 2;
                    int jl;
                    jl = li + r0 - 127;     if (jl >= 0 && jl < 128) sS[r0 * 132 + jl] = ba[hf][0];
                    jl = li + 1 + r0 - 127; if (jl >= 0 && jl < 128) sS[r0 * 132 + jl] = ba[hf][1];
                    jl = li + r1 - 127;     if (jl >= 0 && jl < 128) sS[r1 * 132 + jl] = ba[hf][2];
                    jl = li + 1 + r1 - 127; if (jl >= 0 && jl < 128) sS[r1 * 132 + jl] = ba[hf][3];
                }
            }
        }

        // ---- QK mma ----
        float acc[16][4];
        #pragma unroll
        for (int i = 0; i < 16; i++)
            #pragma unroll
            for (int r = 0; r < 4; r++) acc[i][r] = 0.f;
        {
            const uint32_t bk = sb + A_KHI + (uint32_t)((lane & 15) * AKS + (lane >> 4) * 16);
            #pragma unroll 4
            for (int nb = 0; nb < 8; nb++) {
                #pragma unroll
                for (int ks = 0; ks < 4; ks++) {
                    uint32_t kh[4], kl[4];
                    ldsm_x4(bk + nb * (16 * AKS) + ks * 32, kh);
                    ldsm_x4(bk + (A_KLO - A_KHI) + nb * (16 * AKS) + ks * 32, kl);
                    mma_bf16(acc[2*nb],   qh[ks],  kh[0], kh[2]);
                    mma_bf16(acc[2*nb],   qh[ks],  kl[0], kl[2]);
                    mma_bf16(acc[2*nb],   ql4[ks], kh[0], kh[2]);
                    mma_bf16(acc[2*nb+1], qh[ks],  kh[1], kh[3]);
                    mma_bf16(acc[2*nb+1], qh[ks],  kl[1], kl[3]);
                    mma_bf16(acc[2*nb+1], ql4[ks], kh[1], kh[3]);
                }
            }
        }

        // ---- add band, online softmax ----
        {
            const float* s0 = sS + r0 * 132;
            const float* s1 = sS + r1 * 132;
            #pragma unroll
            for (int nb8 = 0; nb8 < 16; nb8++) {
                const int c = nb8 * 8 + rl * 2;
                acc[nb8][0] += s0[c];     acc[nb8][1] += s0[c + 1];
                acc[nb8][2] += s1[c];     acc[nb8][3] += s1[c + 1];
            }
            float mx0 = -1e30f, mx1 = -1e30f;
            #pragma unroll
            for (int nb8 = 0; nb8 < 16; nb8++) {
                mx0 = fmaxf(mx0, fmaxf(acc[nb8][0], acc[nb8][1]));
                mx1 = fmaxf(mx1, fmaxf(acc[nb8][2], acc[nb8][3]));
            }
            mx0 = fmaxf(mx0, __shfl_xor_sync(0xffffffffu, mx0, 1));
            mx0 = fmaxf(mx0, __shfl_xor_sync(0xffffffffu, mx0, 2));
            mx1 = fmaxf(mx1, __shfl_xor_sync(0xffffffffu, mx1, 1));
            mx1 = fmaxf(mx1, __shfl_xor_sync(0xffffffffu, mx1, 2));
            const float nm0 = fmaxf(m0, mx0), nm1 = fmaxf(m1, mx1);
            const float cr0 = __expf(m0 - nm0), cr1 = __expf(m1 - nm1);
            float s0s = 0.f, s1s = 0.f;
            #pragma unroll
            for (int nb8 = 0; nb8 < 16; nb8++) {
                acc[nb8][0] = __expf(acc[nb8][0] - nm0); s0s += acc[nb8][0];
                acc[nb8][1] = __expf(acc[nb8][1] - nm0); s0s += acc[nb8][1];
                acc[nb8][2] = __expf(acc[nb8][2] - nm1); s1s += acc[nb8][2];
                acc[nb8][3] = __expf(acc[nb8][3] - nm1); s1s += acc[nb8][3];
            }
            s0s += __shfl_xor_sync(0xffffffffu, s0s, 1);
            s0s += __shfl_xor_sync(0xffffffffu, s0s, 2);
            s1s += __shfl_xor_sync(0xffffffffu, s1s, 1);
            s1s += __shfl_xor_sync(0xffffffffu, s1s, 2);
            den0 = den0 * cr0 + s0s; den1 = den1 * cr1 + s1s;
            m0 = nm0; m1 = nm1;
            #pragma unroll
            for (int nd = 0; nd < 8; nd++) {
                o[nd][0] *= cr0; o[nd][1] *= cr0;
                o[nd][2] *= cr1; o[nd][3] *= cr1;
            }
        }

        // ---- PV mma: O += P . V  (V row-major, trans B-frags) ----
        {
            const uint32_t bv = sb + A_VHI + (uint32_t)((lane & 15) * AKS + (lane >> 4) * 16);
            #pragma unroll 2
            for (int kb = 0; kb < 8; kb++) {
                uint32_t ph4[4], pl4[4];
                split_pair(acc[2*kb][0],   acc[2*kb][1],   ph4[0], pl4[0]);
                split_pair(acc[2*kb][2],   acc[2*kb][3],   ph4[1], pl4[1]);
                split_pair(acc[2*kb+1][0], acc[2*kb+1][1], ph4[2], pl4[2]);
                split_pair(acc[2*kb+1][2], acc[2*kb+1][3], ph4[3], pl4[3]);
                #pragma unroll
                for (int dn = 0; dn < 4; dn++) {
                    uint32_t vh[4], vl[4];
                    ldsm_x4t(bv + kb * (16 * AKS) + dn * 32, vh);
                    ldsm_x4t(bv + (A_VLO - A_VHI) + kb * (16 * AKS) + dn * 32, vl);
                    mma_bf16(o[2*dn],   ph4, vh[0], vh[1]);
                    mma_bf16(o[2*dn],   ph4, vl[0], vl[1]);
                    mma_bf16(o[2*dn],   pl4, vh[0], vh[1]);
                    mma_bf16(o[2*dn+1], ph4, vh[2], vh[3]);
                    mma_bf16(o[2*dn+1], ph4, vl[2], vl[3]);
                    mma_bf16(o[2*dn+1], pl4, vh[2], vh[3]);
                }
            }
        }
    }

    // ---- epilogue: normalize, split to bf16 hi/lo ctx ----
    {
        const float inv0 = 1.f / den0, inv1 = 1.f / den1;
        const size_t t0 = tokq + r0, t1 = tokq + r1;
        #pragma unroll
        for (int nd = 0; nd < 8; nd++) {
            const int d = nd * 8 + rl * 2;
            uint32_t hw, lw;
            split_pair(o[nd][0] * inv0, o[nd][1] * inv0, hw, lw);
            *(uint32_t*)(chi + t0 * DD + h * HDp + d) = hw;
            *(uint32_t*)(clo + t0 * DD + h * HDp + d) = lw;
            split_pair(o[nd][2] * inv1, o[nd][3] * inv1, hw, lw);
            *(uint32_t*)(chi + t1 * DD + h * HDp + d) = hw;
            *(uint32_t*)(clo + t1 * DD + h * HDp + d) = lw;
        }
    }
}

// ---------------------------------------------------------------------------
extern "C" void kernel_launch(void* const* d_in, const int* in_sizes, int n_in,
                              void* d_out, int out_size)
{
    const float* x  = (const float*)d_in[0];
    const float* Wq = (const float*)d_in[1];
    const float* bq = (const float*)d_in[2];
    const float* Wk = (const float*)d_in[3];
    const float* bk = (const float*)d_in[4];
    const float* Wv = (const float*)d_in[5];
    const float* bv = (const float*)d_in[6];
    const float* Wo = (const float*)d_in[7];
    const float* bo = (const float*)d_in[8];
    const float* E  = (const float*)d_in[9];
    float* out = (float*)d_out;

    bf16 *xhi, *xlo, *wqh, *wql, *wkh, *wkl, *wvh, *wvl, *woh, *wol;
    bf16 *qhi, *qlo, *khi, *klo, *vhi, *vlo, *ehi, *elo, *chi, *clo;
    cudaGetSymbolAddress((void**)&xhi, g_xhi); cudaGetSymbolAddress((void**)&xlo, g_xlo);
    cudaGetSymbolAddress((void**)&wqh, g_wqh); cudaGetSymbolAddress((void**)&wql, g_wql);
    cudaGetSymbolAddress((void**)&wkh, g_wkh); cudaGetSymbolAddress((void**)&wkl, g_wkl);
    cudaGetSymbolAddress((void**)&wvh, g_wvh); cudaGetSymbolAddress((void**)&wvl, g_wvl);
    cudaGetSymbolAddress((void**)&woh, g_woh); cudaGetSymbolAddress((void**)&wol, g_wol);
    cudaGetSymbolAddress((void**)&qhi, g_qhi); cudaGetSymbolAddress((void**)&qlo, g_qlo);
    cudaGetSymbolAddress((void**)&khi, g_khi); cudaGetSymbolAddress((void**)&klo, g_klo);
    cudaGetSymbolAddress((void**)&vhi, g_vhi); cudaGetSymbolAddress((void**)&vlo, g_vlo);
    cudaGetSymbolAddress((void**)&ehi, g_ehi); cudaGetSymbolAddress((void**)&elo, g_elo);
    cudaGetSymbolAddress((void**)&chi, g_chi); cudaGetSymbolAddress((void**)&clo, g_clo);

    cudaFuncSetAttribute(gemm_tc2_kernel,
                         cudaFuncAttributeMaxDynamicSharedMemorySize, GEMM_SMEM);
    cudaFuncSetAttribute(attn_tc_kernel,
                         cudaFuncAttributeMaxDynamicSharedMemorySize, ATT_SMEM);

    // 0) split inputs into bf16 hi/lo
    cvt_split_kernel<<<MM * DD / 1024, 256>>>(x,  xhi, xlo, MM * DD);
    cvt_split_kernel<<<DD * DD / 1024, 256>>>(Wq, wqh, wql, DD * DD);
    cvt_split_kernel<<<DD * DD / 1024, 256>>>(Wk, wkh, wkl, DD * DD);
    cvt_split_kernel<<<DD * DD / 1024, 256>>>(Wv, wvh, wvl, DD * DD);
    cvt_split_kernel<<<DD * DD / 1024, 256>>>(Wo, woh, wol, DD * DD);
    cvt_split_kernel<<<(NE * HDp + 1023) / 1024, 256>>>(E, ehi, elo, NE * HDp);

    // 1) fused QKV projections -> bf16 hi/lo q(scaled), k, v
    gemm_tc2_kernel<<<dim3(DD / 128, MM / 128, 3), 256, GEMM_SMEM>>>(
        xhi, xlo, wqh, wql, wkh, wkl, wvh, wvl, bq, bk, bv,
        qhi, qlo, khi, klo, vhi, vlo, nullptr, 0.125f, MM, DD, DD);

    // 2) tensor-core flash attention with rel-pos band
    attn_tc_kernel<<<dim3(LL / 128, HH, Bb), 256, ATT_SMEM>>>(
        qhi, qlo, khi, klo, vhi, vlo, ehi, elo, chi, clo);

    // 3) output projection -> fp32 out
    gemm_tc2_kernel<<<dim3(DD / 128, MM / 128, 1), 256, GEMM_SMEM>>>(
        chi, clo, woh, wol, woh, wol, woh, wol, bo, bo, bo,
        nullptr, nullptr, nullptr, nullptr, nullptr, nullptr,
        out, 1.0f, MM, DD, DD);
}